// round 5
// baseline (speedup 1.0000x reference)
#include <cuda_runtime.h>
#include <cuda_bf16.h>
#include <mma.h>
#include <math.h>
#include <stdint.h>

using namespace nvcuda;

// ============================================================================
// CNN(6x conv3d) + LSTM(32) + FC.  wmma bf16 3-term hi/lo split, fp32 accum.
// cp.async double-buffered implicit-GEMM mainloops (BK=32, BN=COUT).
// Activations NDHWC as bf16 hi/lo pairs.  Weights k-major.
// ============================================================================

__device__ __forceinline__ uint32_t smem_u32(const void* p) {
    uint32_t a;
    asm("{ .reg .u64 t; cvta.to.shared.u64 t, %1; cvt.u32.u64 %0, t; }" : "=r"(a) : "l"(p));
    return a;
}
#define CPA16(dst, src, pred) \
    asm volatile("cp.async.ca.shared.global [%0], [%1], 16, %2;" \
                 :: "r"(dst), "l"(src), "r"((pred) ? 16 : 0))
#define CPA8(dst, src, pred) \
    asm volatile("cp.async.ca.shared.global [%0], [%1], 8, %2;" \
                 :: "r"(dst), "l"(src), "r"((pred) ? 8 : 0))
#define CP_COMMIT() asm volatile("cp.async.commit_group;")
#define CP_WAIT1() asm volatile("cp.async.wait_group 1;")
#define CP_WAIT0() asm volatile("cp.async.wait_group 0;")

__device__ __forceinline__ void split2(float a, float b, uint32_t& ph, uint32_t& pl) {
    __nv_bfloat162 h, l;
    h.x = __float2bfloat16_rn(a); h.y = __float2bfloat16_rn(b);
    l.x = __float2bfloat16_rn(a - __bfloat162float(h.x));
    l.y = __float2bfloat16_rn(b - __bfloat162float(h.y));
    ph = *reinterpret_cast<uint32_t*>(&h);
    pl = *reinterpret_cast<uint32_t*>(&l);
}

// ---- bf16 arena ----
#define O_A1H 0LL
#define O_A1L 100663296LL
#define O_A2H 201326592LL
#define O_A2L 222298112LL
#define O_A3H 243269632LL
#define O_A3L 276824064LL
#define O_A4H 310378496LL
#define O_A4L 316669952LL
#define O_A5H 322961408LL
#define O_A5L 331350016LL
#define O_FH  339738624LL
#define O_FL  340787200LL
#define O_W1H 341835776LL
#define O_W1L 341839872LL
#define O_W2H 341843968LL
#define O_W2L 341862400LL
#define O_W3H 341880832LL
#define O_W3L 341917696LL
#define O_W4H 341954560LL
#define O_W4L 342028288LL
#define O_W5H 342102016LL
#define O_W5L 342249472LL
#define O_W6H 342396928LL
#define O_W6L 342691840LL
#define O_WIHH 342986752LL
#define O_WIHL 347181056LL
#define O_WFH 351375360LL
#define O_WFL 351637504LL
#define O_XH  351899648LL
#define O_XL  366579712LL
#define O_HSH 381259776LL
#define O_HSL 381521920LL
#define BH_TOTAL 381784064LL
__device__ __nv_bfloat16 g_bh[BH_TOTAL];

// ---- fp32 arena ----
#define F_XG   0LL
#define F_WTHH 1048576LL
#define F_BG   2097152LL
#define F_H0   2099200LL
#define F_H1   2107392LL
#define F_C    2115584LL
#define F_TOTAL 2123776LL
__device__ float g_f[F_TOTAL];

// ---- prep kernels ----
__global__ void xprep(const float* __restrict__ x, __nv_bfloat16* __restrict__ xh,
                      __nv_bfloat16* __restrict__ xl) {
    long i = ((long)blockIdx.x * blockDim.x + threadIdx.x) * 4;
    float4 v = *(const float4*)(x + i);
    uint2 ph, pl;
    split2(v.x, v.y, ph.x, pl.x);
    split2(v.z, v.w, ph.y, pl.y);
    *(uint2*)(xh + i) = ph;
    *(uint2*)(xl + i) = pl;
}
__global__ void convw_prep(const float* __restrict__ src, __nv_bfloat16* __restrict__ dh,
                           __nv_bfloat16* __restrict__ dl, int CIN, int COUT, int Kpad, float scale) {
    int i = blockIdx.x * blockDim.x + threadIdx.x;
    if (i >= COUT * Kpad) return;
    int co = i / Kpad, kk = i % Kpad;
    float v = 0.f;
    if (kk < CIN * 18) {
        int cin = kk % CIN, tap = kk / CIN;
        v = src[(co * CIN + cin) * 18 + tap] * scale;
    }
    __nv_bfloat16 h = __float2bfloat16_rn(v);
    long o = (long)kk * COUT + co;
    dh[o] = h;
    dl[o] = __float2bfloat16_rn(v - __bfloat162float(h));
}
__global__ void ihw_prep(const float* __restrict__ src, __nv_bfloat16* __restrict__ dh,
                         __nv_bfloat16* __restrict__ dl) {
    int i = blockIdx.x * blockDim.x + threadIdx.x;
    if (i >= 2048 * 2048) return;
    int r = i >> 11, k = i & 2047;
    int g = r >> 9, u = r & 511;
    int n2 = (u << 2) + g;
    int k2 = ((k & 15) << 7) + (k >> 4);
    float v = src[i];
    __nv_bfloat16 h = __float2bfloat16_rn(v);
    long o = (long)k2 * 2048 + n2;
    dh[o] = h;
    dl[o] = __float2bfloat16_rn(v - __bfloat162float(h));
}
__global__ void wf_prep(const float* __restrict__ src, __nv_bfloat16* __restrict__ dh,
                        __nv_bfloat16* __restrict__ dl) {
    int i = blockIdx.x * blockDim.x + threadIdx.x;
    if (i >= 512 * 512) return;
    int n = i >> 9, k = i & 511;
    float v = src[i];
    __nv_bfloat16 h = __float2bfloat16_rn(v);
    long o = (long)k * 512 + n;
    dh[o] = h;
    dl[o] = __float2bfloat16_rn(v - __bfloat162float(h));
}
__global__ void perm_hh(const float* __restrict__ src, float* __restrict__ dst) {
    int i = blockIdx.x * blockDim.x + threadIdx.x;
    if (i < 2048 * 512) {
        int r = i >> 9, k = i & 511;
        int g = r >> 9, u = r & 511;
        dst[k * 2048 + (u << 2) + g] = src[i];
    }
}
__global__ void bias_sum(const float* __restrict__ bi, const float* __restrict__ bh2,
                         float* __restrict__ dst) {
    int i = blockIdx.x * blockDim.x + threadIdx.x;
    if (i < 2048) {
        int g = i >> 9, u = i & 511;
        dst[(u << 2) + g] = bi[i] + bh2[i];
    }
}

// ============================================================================
// cp.async double-buffered implicit-GEMM conv.  CTA: 128(M) x COUT(N), BK=32.
// ============================================================================
template <int CIN, int COUT, int DIN, int HIN, int WIN, int S>
__global__ __launch_bounds__(256) void conv_cp(
    const __nv_bfloat16* __restrict__ ahi, const __nv_bfloat16* __restrict__ alo,
    const __nv_bfloat16* __restrict__ whi, const __nv_bfloat16* __restrict__ wlo,
    const float* __restrict__ bias,
    __nv_bfloat16* __restrict__ ohi, __nv_bfloat16* __restrict__ olo) {
    constexpr int DOUT = DIN - 1;
    constexpr int HOUT = (S == 1) ? HIN : HIN / 2;
    constexpr int WOUT = (S == 1) ? WIN : WIN / 2;
    constexpr int Kpad = (CIN == 4) ? 96 : CIN * 18;
    constexpr int NC = Kpad / 32;
    constexpr int LDA = 40, LDB = COUT + 8, LDC = COUT + 4;
    constexpr int ASZ = 128 * LDA, BSZ = 32 * LDB, STG = 2 * ASZ + 2 * BSZ;
    constexpr int WN = COUT / 32, WM = 8 / WN, MF = 128 / (WM * 16);
    constexpr int L2C = (CIN == 32) ? 5 : (CIN == 64) ? 6 : 7;

    extern __shared__ __align__(128) char smem[];
    __nv_bfloat16* smb = (__nv_bfloat16*)smem;
    float* Cs = (float*)smem;
    uint32_t sb = smem_u32(smem);

    int tid = threadIdx.x, wid = tid >> 5;
    int m0 = blockIdx.x * 128;
    int r = tid >> 1, h = (tid & 1) * 16;
    int m = m0 + r;
    int ow = m % WOUT; int t1 = m / WOUT;
    int oh = t1 % HOUT; int t2 = t1 / HOUT;
    int od = t2 % DOUT; int bb = t2 / DOUT;

    auto issue = [&](int c) {
        int st = c & 1, k0 = c * 32;
        uint32_t aH = sb + (uint32_t)(st * STG + r * LDA + h) * 2;
        uint32_t aL = aH + ASZ * 2;
        if constexpr (CIN == 4) {
#pragma unroll
            for (int i = 0; i < 4; i++) {
                int tap = (k0 + h) / 4 + i;
                int kd = (tap >= 9) ? 1 : 0;
                int r2 = tap - 9 * kd;
                int kh = r2 / 3, kw = r2 - 3 * kh;
                int ih = oh - 1 + kh, iw = ow - 1 + kw;
                bool v = (tap < 18) && (unsigned)ih < (unsigned)HIN && (unsigned)iw < (unsigned)WIN;
                long g = ((((long)bb * DIN + od + kd) * HIN + ih) * WIN + iw) * 4;
                CPA8(aH + i * 8, ahi + g, v);
                CPA8(aL + i * 8, alo + g, v);
            }
        } else {
            int tap = k0 >> L2C;
            int cinb = (k0 & (CIN - 1)) + h;
            int kd = (tap >= 9) ? 1 : 0;
            int r2 = tap - 9 * kd;
            int kh = r2 / 3, kw = r2 - 3 * kh;
            int ih = oh * S - 1 + kh, iw = ow * S - 1 + kw;
            bool v = (unsigned)ih < (unsigned)HIN && (unsigned)iw < (unsigned)WIN;
            long g = ((((long)bb * DIN + od + kd) * HIN + ih) * WIN + iw) * CIN + cinb;
            CPA16(aH, ahi + g, v);
            CPA16(aH + 16, ahi + g + 8, v);
            CPA16(aL, alo + g, v);
            CPA16(aL + 16, alo + g + 8, v);
        }
        uint32_t bH0 = sb + (uint32_t)(st * STG + 2 * ASZ) * 2;
        if constexpr (COUT == 32) {
            if (tid < 128) {
                int kb = tid & 31, nb = (tid >> 5) * 8;
                long g = (long)(k0 + kb) * COUT + nb;
                uint32_t d = bH0 + (uint32_t)(kb * LDB + nb) * 2;
                CPA16(d, whi + g, true);
                CPA16(d + BSZ * 2, wlo + g, true);
            }
        } else if constexpr (COUT == 64) {
            int kb = tid & 31, nb = (tid >> 5) * 8;
            long g = (long)(k0 + kb) * COUT + nb;
            uint32_t d = bH0 + (uint32_t)(kb * LDB + nb) * 2;
            CPA16(d, whi + g, true);
            CPA16(d + BSZ * 2, wlo + g, true);
        } else {
#pragma unroll
            for (int j = 0; j < 2; j++) {
                int kb = tid & 31, nb = (tid >> 5) * 8 + j * 64;
                long g = (long)(k0 + kb) * COUT + nb;
                uint32_t d = bH0 + (uint32_t)(kb * LDB + nb) * 2;
                CPA16(d, whi + g, true);
                CPA16(d + BSZ * 2, wlo + g, true);
            }
        }
    };

    int wm = wid / WN, wn = wid % WN;
    wmma::fragment<wmma::accumulator, 16, 16, 16, float> acc[MF][2];
#pragma unroll
    for (int i = 0; i < MF; i++)
#pragma unroll
        for (int j = 0; j < 2; j++) wmma::fill_fragment(acc[i][j], 0.f);

    issue(0);
    CP_COMMIT();
    for (int c = 0; c < NC; c++) {
        __syncthreads();
        if (c + 1 < NC) { issue(c + 1); CP_COMMIT(); CP_WAIT1(); }
        else CP_WAIT0();
        __syncthreads();
        int st = c & 1;
        const __nv_bfloat16* As = smb + st * STG;
        const __nv_bfloat16* Bs = smb + st * STG + 2 * ASZ;
#pragma unroll
        for (int ks = 0; ks < 2; ks++) {
            wmma::fragment<wmma::matrix_b, 16, 16, 16, __nv_bfloat16, wmma::row_major> fbh[2], fbl[2];
#pragma unroll
            for (int j = 0; j < 2; j++) {
                wmma::load_matrix_sync(fbh[j], Bs + (ks * 16) * LDB + wn * 32 + j * 16, LDB);
                wmma::load_matrix_sync(fbl[j], Bs + BSZ + (ks * 16) * LDB + wn * 32 + j * 16, LDB);
            }
#pragma unroll
            for (int i = 0; i < MF; i++) {
                wmma::fragment<wmma::matrix_a, 16, 16, 16, __nv_bfloat16, wmma::row_major> fah, fal;
                wmma::load_matrix_sync(fah, As + ((wm * MF + i) * 16) * LDA + ks * 16, LDA);
                wmma::load_matrix_sync(fal, As + ASZ + ((wm * MF + i) * 16) * LDA + ks * 16, LDA);
#pragma unroll
                for (int j = 0; j < 2; j++) {
                    wmma::mma_sync(acc[i][j], fah, fbh[j], acc[i][j]);
                    wmma::mma_sync(acc[i][j], fah, fbl[j], acc[i][j]);
                    wmma::mma_sync(acc[i][j], fal, fbh[j], acc[i][j]);
                }
            }
        }
    }
    __syncthreads();
#pragma unroll
    for (int i = 0; i < MF; i++)
#pragma unroll
        for (int j = 0; j < 2; j++)
            wmma::store_matrix_sync(Cs + ((wm * MF + i) * 16) * LDC + wn * 32 + j * 16,
                                    acc[i][j], LDC, wmma::mem_row_major);
    __syncthreads();
    {
        int r2 = tid >> 1, ch0 = (tid & 1) * (COUT / 2);
        long base = (long)(m0 + r2) * COUT + ch0;
#pragma unroll
        for (int c = 0; c < COUT / 2; c += 4) {
            float v0 = Cs[r2 * LDC + ch0 + c]     + bias[ch0 + c];
            float v1 = Cs[r2 * LDC + ch0 + c + 1] + bias[ch0 + c + 1];
            float v2 = Cs[r2 * LDC + ch0 + c + 2] + bias[ch0 + c + 2];
            float v3 = Cs[r2 * LDC + ch0 + c + 3] + bias[ch0 + c + 3];
            v0 = fmaxf(v0, 0.f); v1 = fmaxf(v1, 0.f);
            v2 = fmaxf(v2, 0.f); v3 = fmaxf(v3, 0.f);
            uint2 ph, pl;
            split2(v0, v1, ph.x, pl.x);
            split2(v2, v3, ph.y, pl.y);
            *(uint2*)(ohi + base + c) = ph;
            *(uint2*)(olo + base + c) = pl;
        }
    }
}

// ============================================================================
// cp.async GEMM, fp32 out: C[M x NTOT] = A[M x K](bf16 hi/lo) @ W(k-major).
// CTA: 64 x 128, BK=32, double-buffered.
// ============================================================================
template <int NTOT, int K, bool RELU>
__global__ __launch_bounds__(256) void mm_cp(
    const __nv_bfloat16* __restrict__ ahi, const __nv_bfloat16* __restrict__ alo,
    const __nv_bfloat16* __restrict__ whi, const __nv_bfloat16* __restrict__ wlo,
    const float* __restrict__ bias, float* __restrict__ out) {
    constexpr int NC = K / 32;
    constexpr int LDA = 40, LDB = 136, LDC = 132;
    constexpr int ASZ = 64 * LDA, BSZ = 32 * LDB, STG = 2 * ASZ + 2 * BSZ;

    extern __shared__ __align__(128) char smem[];
    __nv_bfloat16* smb = (__nv_bfloat16*)smem;
    float* Cs = (float*)smem;
    uint32_t sb = smem_u32(smem);

    int tid = threadIdx.x, wid = tid >> 5;
    int m0 = blockIdx.x * 64, n0 = blockIdx.y * 128;
    int r = tid >> 2, h = (tid & 3) * 8;
    long mrow = m0 + r;

    auto issue = [&](int c) {
        int st = c & 1, k0 = c * 32;
        uint32_t aH = sb + (uint32_t)(st * STG + r * LDA + h) * 2;
        long g = mrow * K + k0 + h;
        CPA16(aH, ahi + g, true);
        CPA16(aH + ASZ * 2, alo + g, true);
        uint32_t bH0 = sb + (uint32_t)(st * STG + 2 * ASZ) * 2;
#pragma unroll
        for (int j = 0; j < 2; j++) {
            int kb = tid & 31, nb = (tid >> 5) * 8 + j * 64;
            long gw = (long)(k0 + kb) * NTOT + n0 + nb;
            uint32_t d = bH0 + (uint32_t)(kb * LDB + nb) * 2;
            CPA16(d, whi + gw, true);
            CPA16(d + BSZ * 2, wlo + gw, true);
        }
    };

    int wm = wid >> 2, wn = wid & 3;
    wmma::fragment<wmma::accumulator, 16, 16, 16, float> acc[2][2];
#pragma unroll
    for (int i = 0; i < 2; i++)
#pragma unroll
        for (int j = 0; j < 2; j++) wmma::fill_fragment(acc[i][j], 0.f);

    issue(0);
    CP_COMMIT();
    for (int c = 0; c < NC; c++) {
        __syncthreads();
        if (c + 1 < NC) { issue(c + 1); CP_COMMIT(); CP_WAIT1(); }
        else CP_WAIT0();
        __syncthreads();
        int st = c & 1;
        const __nv_bfloat16* As = smb + st * STG;
        const __nv_bfloat16* Bs = smb + st * STG + 2 * ASZ;
#pragma unroll
        for (int ks = 0; ks < 2; ks++) {
            wmma::fragment<wmma::matrix_b, 16, 16, 16, __nv_bfloat16, wmma::row_major> fbh[2], fbl[2];
#pragma unroll
            for (int j = 0; j < 2; j++) {
                wmma::load_matrix_sync(fbh[j], Bs + (ks * 16) * LDB + wn * 32 + j * 16, LDB);
                wmma::load_matrix_sync(fbl[j], Bs + BSZ + (ks * 16) * LDB + wn * 32 + j * 16, LDB);
            }
#pragma unroll
            for (int i = 0; i < 2; i++) {
                wmma::fragment<wmma::matrix_a, 16, 16, 16, __nv_bfloat16, wmma::row_major> fah, fal;
                wmma::load_matrix_sync(fah, As + ((wm * 2 + i) * 16) * LDA + ks * 16, LDA);
                wmma::load_matrix_sync(fal, As + ASZ + ((wm * 2 + i) * 16) * LDA + ks * 16, LDA);
#pragma unroll
                for (int j = 0; j < 2; j++) {
                    wmma::mma_sync(acc[i][j], fah, fbh[j], acc[i][j]);
                    wmma::mma_sync(acc[i][j], fah, fbl[j], acc[i][j]);
                    wmma::mma_sync(acc[i][j], fal, fbh[j], acc[i][j]);
                }
            }
        }
    }
    __syncthreads();
#pragma unroll
    for (int i = 0; i < 2; i++)
#pragma unroll
        for (int j = 0; j < 2; j++)
            wmma::store_matrix_sync(Cs + ((wm * 2 + i) * 16) * LDC + wn * 32 + j * 16,
                                    acc[i][j], LDC, wmma::mem_row_major);
    __syncthreads();
    {
        int r2 = tid >> 2, ch0 = (tid & 3) * 32;
        long base = (long)(m0 + r2) * NTOT + n0 + ch0;
#pragma unroll
        for (int c = 0; c < 32; c += 4) {
            float4 v;
            v.x = Cs[r2 * LDC + ch0 + c]     + bias[n0 + ch0 + c];
            v.y = Cs[r2 * LDC + ch0 + c + 1] + bias[n0 + ch0 + c + 1];
            v.z = Cs[r2 * LDC + ch0 + c + 2] + bias[n0 + ch0 + c + 2];
            v.w = Cs[r2 * LDC + ch0 + c + 3] + bias[n0 + ch0 + c + 3];
            if (RELU) {
                v.x = fmaxf(v.x, 0.f); v.y = fmaxf(v.y, 0.f);
                v.z = fmaxf(v.z, 0.f); v.w = fmaxf(v.w, 0.f);
            }
            *(float4*)(out + base + c) = v;
        }
    }
}

// ---- LSTM recurrent step (fp32), also emits hs as bf16 hi/lo ----
__global__ void lstm_step(const float* __restrict__ xg, const float* __restrict__ wthh,
                          const float* __restrict__ done, const float* __restrict__ h_in,
                          float* __restrict__ h_out, float* __restrict__ c,
                          __nv_bfloat16* __restrict__ hsh, __nv_bfloat16* __restrict__ hsl,
                          int t) {
    constexpr int PAD = 520;
    __shared__ __align__(16) float sh_h[16 * PAD];
    __shared__ __align__(16) float Bs[16][32];
    int tid = threadIdx.x;
    int n0 = blockIdx.x * 32;
#pragma unroll
    for (int i = 0; i < 16; i++) {
        int idx4 = i * 128 + tid;
        int b = idx4 >> 7;
        int qq = idx4 & 127;
        float keep = 1.f - done[t * 16 + b];
        float4 v = ((const float4*)h_in)[idx4];
        v.x *= keep; v.y *= keep; v.z *= keep; v.w *= keep;
        ((float4*)sh_h)[b * (PAD / 4) + qq] = v;
    }
    __syncthreads();
    int tx = tid & 7, ty = tid >> 3;
    float acc[4] = {0.f, 0.f, 0.f, 0.f};
    for (int k0 = 0; k0 < 512; k0 += 16) {
        {
            int kl = tid >> 3, nl = (tid & 7) * 4;
            *(float4*)&Bs[kl][nl] = *(const float4*)&wthh[(k0 + kl) * 2048 + n0 + nl];
        }
        __syncthreads();
#pragma unroll
        for (int kk = 0; kk < 16; kk++) {
            float a = sh_h[ty * PAD + k0 + kk];
            float4 b4 = *(const float4*)&Bs[kk][tx * 4];
            acc[0] += a * b4.x; acc[1] += a * b4.y;
            acc[2] += a * b4.z; acc[3] += a * b4.w;
        }
        __syncthreads();
    }
    int b = ty;
    int u = (n0 >> 2) + tx;
    float4 xv = *(const float4*)&xg[(t * 16 + b) * 2048 + n0 + tx * 4];
    float ig = acc[0] + xv.x, fg = acc[1] + xv.y, gg = acc[2] + xv.z, og = acc[3] + xv.w;
    float keep = 1.f - done[t * 16 + b];
    float cold = c[b * 512 + u] * keep;
    float si = 1.f / (1.f + expf(-ig));
    float sf = 1.f / (1.f + expf(-fg));
    float so = 1.f / (1.f + expf(-og));
    float cn = sf * cold + si * tanhf(gg);
    float hn = so * tanhf(cn);
    c[b * 512 + u] = cn;
    h_out[b * 512 + u] = hn;
    long hsidx = (long)(t * 16 + b) * 512 + u;
    __nv_bfloat16 hh = __float2bfloat16_rn(hn);
    hsh[hsidx] = hh;
    hsl[hsidx] = __float2bfloat16_rn(hn - __bfloat162float(hh));
}

// ---------------------------------------------------------------------------
extern "C" void kernel_launch(void* const* d_in, const int* in_sizes, int n_in,
                              void* d_out, int out_size) {
    (void)in_sizes; (void)n_in; (void)out_size;
    __nv_bfloat16* bh = nullptr;
    float* fa = nullptr;
    cudaGetSymbolAddress((void**)&bh, g_bh);
    cudaGetSymbolAddress((void**)&fa, g_f);

    const float* x    = (const float*)d_in[0];
    const float* done = (const float*)d_in[1];
    const float* h0   = (const float*)d_in[2];
    const float* c0   = (const float*)d_in[3];
    const float* w11  = (const float*)d_in[4];
    const float* b11  = (const float*)d_in[5];
    const float* w12  = (const float*)d_in[6];
    const float* b12  = (const float*)d_in[7];
    const float* w21  = (const float*)d_in[8];
    const float* b21  = (const float*)d_in[9];
    const float* w22  = (const float*)d_in[10];
    const float* b22  = (const float*)d_in[11];
    const float* w31  = (const float*)d_in[12];
    const float* b31  = (const float*)d_in[13];
    const float* w32  = (const float*)d_in[14];
    const float* b32  = (const float*)d_in[15];
    const float* W_ih = (const float*)d_in[16];
    const float* W_hh = (const float*)d_in[17];
    const float* b_ih = (const float*)d_in[18];
    const float* b_hh = (const float*)d_in[19];
    const float* Wf   = (const float*)d_in[20];
    const float* bf   = (const float*)d_in[21];
    float* out = (float*)d_out;

    auto L1k = conv_cp<4, 32, 7, 32, 32, 1>;
    auto L2k = conv_cp<32, 32, 6, 32, 32, 2>;
    auto L3k = conv_cp<32, 64, 5, 16, 16, 1>;
    auto L4k = conv_cp<64, 64, 4, 16, 16, 2>;
    auto L5k = conv_cp<64, 128, 3, 8, 8, 1>;
    auto L6k = conv_cp<128, 128, 2, 8, 8, 2>;
    auto IHk = mm_cp<2048, 2048, false>;
    auto FCk = mm_cp<512, 512, true>;
    cudaFuncSetAttribute(L1k, cudaFuncAttributeMaxDynamicSharedMemorySize, 51200);
    cudaFuncSetAttribute(L2k, cudaFuncAttributeMaxDynamicSharedMemorySize, 51200);
    cudaFuncSetAttribute(L3k, cudaFuncAttributeMaxDynamicSharedMemorySize, 59392);
    cudaFuncSetAttribute(L4k, cudaFuncAttributeMaxDynamicSharedMemorySize, 59392);
    cudaFuncSetAttribute(L5k, cudaFuncAttributeMaxDynamicSharedMemorySize, 75776);
    cudaFuncSetAttribute(L6k, cudaFuncAttributeMaxDynamicSharedMemorySize, 75776);
    cudaFuncSetAttribute(IHk, cudaFuncAttributeMaxDynamicSharedMemorySize, 55296);
    cudaFuncSetAttribute(FCk, cudaFuncAttributeMaxDynamicSharedMemorySize, 55296);

    // ---- prep ----
    xprep<<<14336, 256>>>(x, bh + O_XH, bh + O_XL);
    convw_prep<<<12, 256>>>(w11, bh + O_W1H, bh + O_W1L, 4, 32, 96, 1.f / 255.f);
    convw_prep<<<72, 256>>>(w12, bh + O_W2H, bh + O_W2L, 32, 32, 576, 1.f);
    convw_prep<<<144, 256>>>(w21, bh + O_W3H, bh + O_W3L, 32, 64, 576, 1.f);
    convw_prep<<<288, 256>>>(w22, bh + O_W4H, bh + O_W4L, 64, 64, 1152, 1.f);
    convw_prep<<<576, 256>>>(w31, bh + O_W5H, bh + O_W5L, 64, 128, 1152, 1.f);
    convw_prep<<<1152, 256>>>(w32, bh + O_W6H, bh + O_W6L, 128, 128, 2304, 1.f);
    ihw_prep<<<16384, 256>>>(W_ih, bh + O_WIHH, bh + O_WIHL);
    wf_prep<<<1024, 256>>>(Wf, bh + O_WFH, bh + O_WFL);
    perm_hh<<<4096, 256>>>(W_hh, fa + F_WTHH);
    bias_sum<<<8, 256>>>(b_ih, b_hh, fa + F_BG);
    cudaMemcpyAsync(fa + F_H0, h0, 8192 * sizeof(float), cudaMemcpyDeviceToDevice, 0);
    cudaMemcpyAsync(fa + F_C,  c0, 8192 * sizeof(float), cudaMemcpyDeviceToDevice, 0);

    // ---- conv stack ----
    L1k<<<24576, 256, 51200>>>(bh + O_XH, bh + O_XL, bh + O_W1H, bh + O_W1L, b11, bh + O_A1H, bh + O_A1L);
    L2k<<<5120, 256, 51200>>>(bh + O_A1H, bh + O_A1L, bh + O_W2H, bh + O_W2L, b12, bh + O_A2H, bh + O_A2L);
    L3k<<<4096, 256, 59392>>>(bh + O_A2H, bh + O_A2L, bh + O_W3H, bh + O_W3L, b21, bh + O_A3H, bh + O_A3L);
    L4k<<<768, 256, 59392>>>(bh + O_A3H, bh + O_A3L, bh + O_W4H, bh + O_W4L, b22, bh + O_A4H, bh + O_A4L);
    L5k<<<512, 256, 75776>>>(bh + O_A4H, bh + O_A4L, bh + O_W5H, bh + O_W5L, b31, bh + O_A5H, bh + O_A5L);
    L6k<<<64, 256, 75776>>>(bh + O_A5H, bh + O_A5L, bh + O_W6H, bh + O_W6L, b32, bh + O_FH, bh + O_FL);

    // ---- LSTM input GEMM (512 x 2048 x 2048) ----
    IHk<<<dim3(8, 16), 256, 55296>>>(bh + O_FH, bh + O_FL, bh + O_WIHH, bh + O_WIHL,
                                     fa + F_BG, fa + F_XG);

    // ---- 32 recurrent steps ----
    for (int t = 0; t < 32; t++) {
        float* hin  = fa + ((t & 1) ? F_H1 : F_H0);
        float* hout = fa + ((t & 1) ? F_H0 : F_H1);
        lstm_step<<<64, 128>>>(fa + F_XG, fa + F_WTHH, done, hin, hout,
                               fa + F_C, bh + O_HSH, bh + O_HSL, t);
    }

    // ---- final FC + relu into d_out ----
    FCk<<<dim3(8, 4), 256, 55296>>>(bh + O_HSH, bh + O_HSL, bh + O_WFH, bh + O_WFL,
                                    bf, out);

    // ---- hT, cT ----
    cudaMemcpyAsync(out + 262144, fa + F_H0, 8192 * sizeof(float),
                    cudaMemcpyDeviceToDevice, 0);
    cudaMemcpyAsync(out + 270336, fa + F_C, 8192 * sizeof(float),
                    cudaMemcpyDeviceToDevice, 0);
}

// round 6
// speedup vs baseline: 1.0644x; 1.0644x over previous
#include <cuda_runtime.h>
#include <cuda_bf16.h>
#include <mma.h>
#include <stdint.h>

using namespace nvcuda;

// ============================================================================
// CNN(6x conv3d) + LSTM(32) + FC.  wmma bf16 3-term hi/lo split, fp32 accum.
// Register-double-buffered implicit-GEMM mainloops, static smem, BN=COUT.
// Activations NDHWC as bf16 hi/lo pairs.  Weights k-major.
// ============================================================================

__device__ __forceinline__ void split2(float a, float b, uint32_t& ph, uint32_t& pl) {
    __nv_bfloat162 h, l;
    h.x = __float2bfloat16_rn(a); h.y = __float2bfloat16_rn(b);
    l.x = __float2bfloat16_rn(a - __bfloat162float(h.x));
    l.y = __float2bfloat16_rn(b - __bfloat162float(h.y));
    ph = *reinterpret_cast<uint32_t*>(&h);
    pl = *reinterpret_cast<uint32_t*>(&l);
}

// ---- bf16 arena ----
#define O_A1H 0LL
#define O_A1L 100663296LL
#define O_A2H 201326592LL
#define O_A2L 222298112LL
#define O_A3H 243269632LL
#define O_A3L 276824064LL
#define O_A4H 310378496LL
#define O_A4L 316669952LL
#define O_A5H 322961408LL
#define O_A5L 331350016LL
#define O_FH  339738624LL
#define O_FL  340787200LL
#define O_W1H 341835776LL
#define O_W1L 341839872LL
#define O_W2H 341843968LL
#define O_W2L 341862400LL
#define O_W3H 341880832LL
#define O_W3L 341917696LL
#define O_W4H 341954560LL
#define O_W4L 342028288LL
#define O_W5H 342102016LL
#define O_W5L 342249472LL
#define O_W6H 342396928LL
#define O_W6L 342691840LL
#define O_WIHH 342986752LL
#define O_WIHL 347181056LL
#define O_WFH 351375360LL
#define O_WFL 351637504LL
#define O_XH  351899648LL
#define O_XL  366579712LL
#define O_HSH 381259776LL
#define O_HSL 381521920LL
#define BH_TOTAL 381784064LL
__device__ __nv_bfloat16 g_bh[BH_TOTAL];

// ---- fp32 arena ----
#define F_XG   0LL
#define F_WTHH 1048576LL
#define F_BG   2097152LL
#define F_H0   2099200LL
#define F_H1   2107392LL
#define F_C    2115584LL
#define F_TOTAL 2123776LL
__device__ float g_f[F_TOTAL];

// ---- prep kernels ----
__global__ void xprep(const float* __restrict__ x, __nv_bfloat16* __restrict__ xh,
                      __nv_bfloat16* __restrict__ xl) {
    long i = ((long)blockIdx.x * blockDim.x + threadIdx.x) * 4;
    float4 v = *(const float4*)(x + i);
    uint2 ph, pl;
    split2(v.x, v.y, ph.x, pl.x);
    split2(v.z, v.w, ph.y, pl.y);
    *(uint2*)(xh + i) = ph;
    *(uint2*)(xl + i) = pl;
}
__global__ void convw_prep(const float* __restrict__ src, __nv_bfloat16* __restrict__ dh,
                           __nv_bfloat16* __restrict__ dl, int CIN, int COUT, int Kpad, float scale) {
    int i = blockIdx.x * blockDim.x + threadIdx.x;
    if (i >= COUT * Kpad) return;
    int co = i / Kpad, kk = i % Kpad;
    float v = 0.f;
    if (kk < CIN * 18) {
        int cin = kk % CIN, tap = kk / CIN;
        v = src[(co * CIN + cin) * 18 + tap] * scale;
    }
    __nv_bfloat16 h = __float2bfloat16_rn(v);
    long o = (long)kk * COUT + co;
    dh[o] = h;
    dl[o] = __float2bfloat16_rn(v - __bfloat162float(h));
}
// Smem-tiled W_ih permutation: dst[k2*2048 + n2], k2 = sp*128+c (k=c*16+sp),
// n2 = u*4+g (row r = g*512+u).  Coalesced reads + writes.
__global__ void ihw_prep_t(const float* __restrict__ src,
                           __nv_bfloat16* __restrict__ dh, __nv_bfloat16* __restrict__ dl) {
    extern __shared__ __nv_bfloat16 ts[];           // [2][128][136]
    __nv_bfloat16* TH = ts;
    __nv_bfloat16* TL = ts + 128 * 136;
    int tid = threadIdx.x;
    int kb = blockIdx.x * 128, nbv = blockIdx.y * 128;
    {
        int n2 = nbv + (tid >> 1);
        int g = n2 & 3, u = n2 >> 2;
        const float* srow = src + (long)(g * 512 + u) * 2048 + kb + (tid & 1) * 64;
        int klo = (tid & 1) * 64, col = tid >> 1;
#pragma unroll
        for (int q = 0; q < 16; q++) {
            float4 v = *(const float4*)(srow + q * 4);
            float vv[4] = {v.x, v.y, v.z, v.w};
#pragma unroll
            for (int e = 0; e < 4; e++) {
                __nv_bfloat16 hh = __float2bfloat16_rn(vv[e]);
                TH[(klo + q * 4 + e) * 136 + col] = hh;
                TL[(klo + q * 4 + e) * 136 + col] =
                    __float2bfloat16_rn(vv[e] - __bfloat162float(hh));
            }
        }
    }
    __syncthreads();
    {
        int kl = tid >> 1, nh = (tid & 1) * 64;
        int cl = kl >> 4, sp = kl & 15;
        int k2 = sp * 128 + (kb >> 4) + cl;
        long base = (long)k2 * 2048 + nbv + nh;
#pragma unroll
        for (int q = 0; q < 8; q++) {
            *(uint4*)(dh + base + q * 8) = *(const uint4*)(TH + kl * 136 + nh + q * 8);
            *(uint4*)(dl + base + q * 8) = *(const uint4*)(TL + kl * 136 + nh + q * 8);
        }
    }
}
__global__ void wf_prep(const float* __restrict__ src, __nv_bfloat16* __restrict__ dh,
                        __nv_bfloat16* __restrict__ dl) {
    int i = blockIdx.x * blockDim.x + threadIdx.x;
    if (i >= 512 * 512) return;
    int n = i >> 9, k = i & 511;
    float v = src[i];
    __nv_bfloat16 h = __float2bfloat16_rn(v);
    long o = (long)k * 512 + n;
    dh[o] = h;
    dl[o] = __float2bfloat16_rn(v - __bfloat162float(h));
}
__global__ void perm_hh(const float* __restrict__ src, float* __restrict__ dst) {
    int i = blockIdx.x * blockDim.x + threadIdx.x;
    if (i < 2048 * 512) {
        int r = i >> 9, k = i & 511;
        int g = r >> 9, u = r & 511;
        dst[k * 2048 + (u << 2) + g] = src[i];
    }
}
__global__ void bias_sum(const float* __restrict__ bi, const float* __restrict__ bh2,
                         float* __restrict__ dst) {
    int i = blockIdx.x * blockDim.x + threadIdx.x;
    if (i < 2048) {
        int g = i >> 9, u = i & 511;
        dst[(u << 2) + g] = bi[i] + bh2[i];
    }
}

// ============================================================================
// Reg-double-buffered wmma implicit-GEMM conv.  CTA: BM(M) x COUT(N), BK=16.
// BM=128 (COUT<=64) or 64 (COUT=128).  Static smem, single buffer.
// ============================================================================
template <int CIN, int COUT, int DIN, int HIN, int WIN, int S>
__global__ __launch_bounds__(256) void conv_wm2(
    const __nv_bfloat16* __restrict__ ahi, const __nv_bfloat16* __restrict__ alo,
    const __nv_bfloat16* __restrict__ whi, const __nv_bfloat16* __restrict__ wlo,
    const float* __restrict__ bias,
    __nv_bfloat16* __restrict__ ohi, __nv_bfloat16* __restrict__ olo) {
    constexpr int DOUT = DIN - 1;
    constexpr int HOUT = (S == 1) ? HIN : HIN / 2;
    constexpr int WOUT = (S == 1) ? WIN : WIN / 2;
    constexpr int Kpad = (CIN == 4) ? 80 : CIN * 18;
    constexpr int NC = Kpad / 16;
    constexpr int BM = (COUT >= 128) ? 64 : 128;
    constexpr int TPR = 256 / BM;               // threads per A-row: 2 or 4
    constexpr int HS = 16 / TPR;                // k-span per thread: 8 or 4
    constexpr int WN = (COUT >= 128) ? 4 : (COUT / 32);
    constexpr int WM = 8 / WN, MF = BM / (WM * 16);
    constexpr int LDA = 24, LDB = COUT + 8, LDC = COUT + 4;
    constexpr int ASZ = BM * LDA, BSZ = 16 * LDB;
    constexpr int L2C = (CIN == 32) ? 5 : ((CIN == 64) ? 6 : 7);
    constexpr int LOADSZ = (2 * ASZ + 2 * BSZ) * 2;
    constexpr int CSZ = BM * LDC * 4;
    constexpr int SMSZ = (LOADSZ > CSZ) ? LOADSZ : CSZ;

    __shared__ __align__(16) char sm[SMSZ];
    __nv_bfloat16* AsH = (__nv_bfloat16*)sm;
    __nv_bfloat16* AsL = AsH + ASZ;
    __nv_bfloat16* BsH = AsL + ASZ;
    __nv_bfloat16* BsL = BsH + BSZ;
    float* Cs = (float*)sm;

    int tid = threadIdx.x, wid = tid >> 5;
    int m0 = blockIdx.x * BM;
    int r = tid / TPR;
    int h = (tid % TPR) * HS;
    int m = m0 + r;
    int ow = m % WOUT; int t1 = m / WOUT;
    int oh = t1 % HOUT; int t2 = t1 / HOUT;
    int od = t2 % DOUT; int bb = t2 / DOUT;

    constexpr int TPK = COUT / 8;
    int kb = tid / TPK, nb = (tid % TPK) * 8;
    bool bact = kb < 16;

    auto lda_r = [&](int c, uint4& vh, uint4& vl) {
        vh = make_uint4(0u, 0u, 0u, 0u); vl = vh;
        if constexpr (CIN == 4) {
            int kk = c * 16 + h;
#pragma unroll
            for (int t = 0; t < 2; t++) {
                int tap = kk / 4 + t;
                if (tap < 18) {
                    int kd = (tap >= 9) ? 1 : 0; int rr = tap - 9 * kd;
                    int kh = rr / 3, kw = rr - 3 * kh;
                    int ih = oh - 1 + kh, iw = ow - 1 + kw;
                    if ((unsigned)ih < (unsigned)HIN && (unsigned)iw < (unsigned)WIN) {
                        long g = ((((long)bb * DIN + od + kd) * HIN + ih) * WIN + iw) * 4;
                        uint2 xh = *(const uint2*)(ahi + g);
                        uint2 xl = *(const uint2*)(alo + g);
                        if (t == 0) { vh.x = xh.x; vh.y = xh.y; vl.x = xl.x; vl.y = xl.y; }
                        else        { vh.z = xh.x; vh.w = xh.y; vl.z = xl.x; vl.w = xl.y; }
                    }
                }
            }
        } else {
            int kk = c * 16 + h;
            int tap = kk >> L2C, cin = kk & (CIN - 1);
            int kd = (tap >= 9) ? 1 : 0; int rr = tap - 9 * kd;
            int kh = rr / 3, kw = rr - 3 * kh;
            int ih = oh * S - 1 + kh, iw = ow * S - 1 + kw;
            if ((unsigned)ih < (unsigned)HIN && (unsigned)iw < (unsigned)WIN) {
                long g = ((((long)bb * DIN + od + kd) * HIN + ih) * WIN + iw) * CIN + cin;
                if constexpr (TPR == 2) {
                    vh = *(const uint4*)(ahi + g);
                    vl = *(const uint4*)(alo + g);
                } else {
                    uint2 xh = *(const uint2*)(ahi + g);
                    uint2 xl = *(const uint2*)(alo + g);
                    vh.x = xh.x; vh.y = xh.y; vl.x = xl.x; vl.y = xl.y;
                }
            }
        }
    };
    auto ldb_r = [&](int c, uint4& wh, uint4& wl) {
        if (bact) {
            long g = (long)(c * 16 + kb) * COUT + nb;
            wh = *(const uint4*)(whi + g);
            wl = *(const uint4*)(wlo + g);
        }
    };

    int wm = wid / WN, wn = wid % WN;
    wmma::fragment<wmma::accumulator, 16, 16, 16, float> acc[MF][2];
#pragma unroll
    for (int i = 0; i < MF; i++)
#pragma unroll
        for (int j = 0; j < 2; j++) wmma::fill_fragment(acc[i][j], 0.f);

    uint4 ah = make_uint4(0,0,0,0), al = ah, wh = ah, wl = ah;
    uint4 nah = ah, nal = ah, nwh = ah, nwl = ah;
    lda_r(0, ah, al); ldb_r(0, wh, wl);
    for (int c = 0; c < NC; c++) {
        __syncthreads();
        if constexpr (TPR == 2) {
            *(uint4*)(AsH + r * LDA + h) = ah;
            *(uint4*)(AsL + r * LDA + h) = al;
        } else {
            *(uint2*)(AsH + r * LDA + h) = make_uint2(ah.x, ah.y);
            *(uint2*)(AsL + r * LDA + h) = make_uint2(al.x, al.y);
        }
        if (bact) {
            *(uint4*)(BsH + kb * LDB + nb) = wh;
            *(uint4*)(BsL + kb * LDB + nb) = wl;
        }
        if (c + 1 < NC) { lda_r(c + 1, nah, nal); ldb_r(c + 1, nwh, nwl); }
        __syncthreads();
        wmma::fragment<wmma::matrix_b, 16, 16, 16, __nv_bfloat16, wmma::row_major> fbh[2], fbl[2];
#pragma unroll
        for (int j = 0; j < 2; j++) {
            wmma::load_matrix_sync(fbh[j], BsH + wn * 32 + j * 16, LDB);
            wmma::load_matrix_sync(fbl[j], BsL + wn * 32 + j * 16, LDB);
        }
#pragma unroll
        for (int i = 0; i < MF; i++) {
            wmma::fragment<wmma::matrix_a, 16, 16, 16, __nv_bfloat16, wmma::row_major> fah, fal;
            wmma::load_matrix_sync(fah, AsH + ((wm * MF + i) * 16) * LDA, LDA);
            wmma::load_matrix_sync(fal, AsL + ((wm * MF + i) * 16) * LDA, LDA);
#pragma unroll
            for (int j = 0; j < 2; j++) {
                wmma::mma_sync(acc[i][j], fah, fbh[j], acc[i][j]);
                wmma::mma_sync(acc[i][j], fah, fbl[j], acc[i][j]);
                wmma::mma_sync(acc[i][j], fal, fbh[j], acc[i][j]);
            }
        }
        ah = nah; al = nal; wh = nwh; wl = nwl;
    }
    __syncthreads();
#pragma unroll
    for (int i = 0; i < MF; i++)
#pragma unroll
        for (int j = 0; j < 2; j++)
            wmma::store_matrix_sync(Cs + ((wm * MF + i) * 16) * LDC + wn * 32 + j * 16,
                                    acc[i][j], LDC, wmma::mem_row_major);
    __syncthreads();
    {
        int r2 = tid / TPR, ch0 = (tid % TPR) * (COUT / TPR);
        long base = (long)(m0 + r2) * COUT + ch0;
#pragma unroll
        for (int c = 0; c < COUT / TPR; c += 4) {
            float v0 = Cs[r2 * LDC + ch0 + c]     + bias[ch0 + c];
            float v1 = Cs[r2 * LDC + ch0 + c + 1] + bias[ch0 + c + 1];
            float v2 = Cs[r2 * LDC + ch0 + c + 2] + bias[ch0 + c + 2];
            float v3 = Cs[r2 * LDC + ch0 + c + 3] + bias[ch0 + c + 3];
            v0 = fmaxf(v0, 0.f); v1 = fmaxf(v1, 0.f);
            v2 = fmaxf(v2, 0.f); v3 = fmaxf(v3, 0.f);
            uint2 ph, pl;
            split2(v0, v1, ph.x, pl.x);
            split2(v2, v3, ph.y, pl.y);
            *(uint2*)(ohi + base + c) = ph;
            *(uint2*)(olo + base + c) = pl;
        }
    }
}

// ============================================================================
// Reg-double-buffered wmma GEMM, fp32 out.  CTA: 64 x 128, BK=16.
// ============================================================================
template <int NTOT, int K, bool RELU>
__global__ __launch_bounds__(256) void mm_wm2(
    const __nv_bfloat16* __restrict__ ahi, const __nv_bfloat16* __restrict__ alo,
    const __nv_bfloat16* __restrict__ whi, const __nv_bfloat16* __restrict__ wlo,
    const float* __restrict__ bias, float* __restrict__ out) {
    constexpr int NC = K / 16;
    constexpr int LDA = 24, LDB = 136, LDC = 132;
    constexpr int ASZ = 64 * LDA, BSZ = 16 * LDB;
    constexpr int LOADSZ = (2 * ASZ + 2 * BSZ) * 2;
    constexpr int CSZ = 64 * LDC * 4;
    constexpr int SMSZ = (LOADSZ > CSZ) ? LOADSZ : CSZ;

    __shared__ __align__(16) char sm[SMSZ];
    __nv_bfloat16* AsH = (__nv_bfloat16*)sm;
    __nv_bfloat16* AsL = AsH + ASZ;
    __nv_bfloat16* BsH = AsL + ASZ;
    __nv_bfloat16* BsL = BsH + BSZ;
    float* Cs = (float*)sm;

    int tid = threadIdx.x, wid = tid >> 5;
    int m0 = blockIdx.x * 64, n0 = blockIdx.y * 128;
    int r = tid >> 2, h = (tid & 3) * 4;
    long mrow = m0 + r;
    int kb = tid >> 4, nb = (tid & 15) * 8;

    auto lda_r = [&](int c, uint2& vh, uint2& vl) {
        long g = mrow * K + c * 16 + h;
        vh = *(const uint2*)(ahi + g);
        vl = *(const uint2*)(alo + g);
    };
    auto ldb_r = [&](int c, uint4& wh, uint4& wl) {
        long g = (long)(c * 16 + kb) * NTOT + n0 + nb;
        wh = *(const uint4*)(whi + g);
        wl = *(const uint4*)(wlo + g);
    };

    int wm = wid >> 2, wn = wid & 3;
    wmma::fragment<wmma::accumulator, 16, 16, 16, float> acc[2][2];
#pragma unroll
    for (int i = 0; i < 2; i++)
#pragma unroll
        for (int j = 0; j < 2; j++) wmma::fill_fragment(acc[i][j], 0.f);

    uint2 ah, al, nah = make_uint2(0,0), nal = nah;
    uint4 wh, wl, nwh = make_uint4(0,0,0,0), nwl = nwh;
    lda_r(0, ah, al); ldb_r(0, wh, wl);
    for (int c = 0; c < NC; c++) {
        __syncthreads();
        *(uint2*)(AsH + r * LDA + h) = ah;
        *(uint2*)(AsL + r * LDA + h) = al;
        *(uint4*)(BsH + kb * LDB + nb) = wh;
        *(uint4*)(BsL + kb * LDB + nb) = wl;
        if (c + 1 < NC) { lda_r(c + 1, nah, nal); ldb_r(c + 1, nwh, nwl); }
        __syncthreads();
        wmma::fragment<wmma::matrix_b, 16, 16, 16, __nv_bfloat16, wmma::row_major> fbh[2], fbl[2];
#pragma unroll
        for (int j = 0; j < 2; j++) {
            wmma::load_matrix_sync(fbh[j], BsH + wn * 32 + j * 16, LDB);
            wmma::load_matrix_sync(fbl[j], BsL + wn * 32 + j * 16, LDB);
        }
#pragma unroll
        for (int i = 0; i < 2; i++) {
            wmma::fragment<wmma::matrix_a, 16, 16, 16, __nv_bfloat16, wmma::row_major> fah, fal;
            wmma::load_matrix_sync(fah, AsH + ((wm * 2 + i) * 16) * LDA, LDA);
            wmma::load_matrix_sync(fal, AsL + ((wm * 2 + i) * 16) * LDA, LDA);
#pragma unroll
            for (int j = 0; j < 2; j++) {
                wmma::mma_sync(acc[i][j], fah, fbh[j], acc[i][j]);
                wmma::mma_sync(acc[i][j], fah, fbl[j], acc[i][j]);
                wmma::mma_sync(acc[i][j], fal, fbh[j], acc[i][j]);
            }
        }
        ah = nah; al = nal; wh = nwh; wl = nwl;
    }
    __syncthreads();
#pragma unroll
    for (int i = 0; i < 2; i++)
#pragma unroll
        for (int j = 0; j < 2; j++)
            wmma::store_matrix_sync(Cs + ((wm * 2 + i) * 16) * LDC + wn * 32 + j * 16,
                                    acc[i][j], LDC, wmma::mem_row_major);
    __syncthreads();
    {
        int r2 = tid >> 2, ch0 = (tid & 3) * 32;
        long base = (long)(m0 + r2) * NTOT + n0 + ch0;
#pragma unroll
        for (int c = 0; c < 32; c += 4) {
            float4 v;
            v.x = Cs[r2 * LDC + ch0 + c]     + bias[n0 + ch0 + c];
            v.y = Cs[r2 * LDC + ch0 + c + 1] + bias[n0 + ch0 + c + 1];
            v.z = Cs[r2 * LDC + ch0 + c + 2] + bias[n0 + ch0 + c + 2];
            v.w = Cs[r2 * LDC + ch0 + c + 3] + bias[n0 + ch0 + c + 3];
            if (RELU) {
                v.x = fmaxf(v.x, 0.f); v.y = fmaxf(v.y, 0.f);
                v.z = fmaxf(v.z, 0.f); v.w = fmaxf(v.w, 0.f);
            }
            *(float4*)(out + base + c) = v;
        }
    }
}

// ---- LSTM recurrent step (fp32), emits hs as bf16 hi/lo ----
__global__ void lstm_step(const float* __restrict__ xg, const float* __restrict__ wthh,
                          const float* __restrict__ done, const float* __restrict__ h_in,
                          float* __restrict__ h_out, float* __restrict__ c,
                          __nv_bfloat16* __restrict__ hsh, __nv_bfloat16* __restrict__ hsl,
                          int t) {
    constexpr int PAD = 520;
    __shared__ __align__(16) float sh_h[16 * PAD];
    __shared__ __align__(16) float Bs[16][32];
    int tid = threadIdx.x;
    int n0 = blockIdx.x * 32;
#pragma unroll
    for (int i = 0; i < 16; i++) {
        int idx4 = i * 128 + tid;
        int b = idx4 >> 7;
        int qq = idx4 & 127;
        float keep = 1.f - done[t * 16 + b];
        float4 v = ((const float4*)h_in)[idx4];
        v.x *= keep; v.y *= keep; v.z *= keep; v.w *= keep;
        ((float4*)sh_h)[b * (PAD / 4) + qq] = v;
    }
    __syncthreads();
    int tx = tid & 7, ty = tid >> 3;
    float acc[4] = {0.f, 0.f, 0.f, 0.f};
    for (int k0 = 0; k0 < 512; k0 += 16) {
        {
            int kl = tid >> 3, nl = (tid & 7) * 4;
            *(float4*)&Bs[kl][nl] = *(const float4*)&wthh[(k0 + kl) * 2048 + n0 + nl];
        }
        __syncthreads();
#pragma unroll
        for (int kk = 0; kk < 16; kk++) {
            float a = sh_h[ty * PAD + k0 + kk];
            float4 b4 = *(const float4*)&Bs[kk][tx * 4];
            acc[0] += a * b4.x; acc[1] += a * b4.y;
            acc[2] += a * b4.z; acc[3] += a * b4.w;
        }
        __syncthreads();
    }
    int b = ty;
    int u = (n0 >> 2) + tx;
    float4 xv = *(const float4*)&xg[(t * 16 + b) * 2048 + n0 + tx * 4];
    float ig = acc[0] + xv.x, fg = acc[1] + xv.y, gg = acc[2] + xv.z, og = acc[3] + xv.w;
    float keep = 1.f - done[t * 16 + b];
    float cold = c[b * 512 + u] * keep;
    float si = 1.f / (1.f + expf(-ig));
    float sf = 1.f / (1.f + expf(-fg));
    float so = 1.f / (1.f + expf(-og));
    float cn = sf * cold + si * tanhf(gg);
    float hn = so * tanhf(cn);
    c[b * 512 + u] = cn;
    h_out[b * 512 + u] = hn;
    long hsidx = (long)(t * 16 + b) * 512 + u;
    __nv_bfloat16 hh = __float2bfloat16_rn(hn);
    hsh[hsidx] = hh;
    hsl[hsidx] = __float2bfloat16_rn(hn - __bfloat162float(hh));
}

// ---------------------------------------------------------------------------
extern "C" void kernel_launch(void* const* d_in, const int* in_sizes, int n_in,
                              void* d_out, int out_size) {
    (void)in_sizes; (void)n_in; (void)out_size;
    __nv_bfloat16* bh = nullptr;
    float* fa = nullptr;
    cudaGetSymbolAddress((void**)&bh, g_bh);
    cudaGetSymbolAddress((void**)&fa, g_f);

    const float* x    = (const float*)d_in[0];
    const float* done = (const float*)d_in[1];
    const float* h0   = (const float*)d_in[2];
    const float* c0   = (const float*)d_in[3];
    const float* w11  = (const float*)d_in[4];
    const float* b11  = (const float*)d_in[5];
    const float* w12  = (const float*)d_in[6];
    const float* b12  = (const float*)d_in[7];
    const float* w21  = (const float*)d_in[8];
    const float* b21  = (const float*)d_in[9];
    const float* w22  = (const float*)d_in[10];
    const float* b22  = (const float*)d_in[11];
    const float* w31  = (const float*)d_in[12];
    const float* b31  = (const float*)d_in[13];
    const float* w32  = (const float*)d_in[14];
    const float* b32  = (const float*)d_in[15];
    const float* W_ih = (const float*)d_in[16];
    const float* W_hh = (const float*)d_in[17];
    const float* b_ih = (const float*)d_in[18];
    const float* b_hh = (const float*)d_in[19];
    const float* Wf   = (const float*)d_in[20];
    const float* bf   = (const float*)d_in[21];
    float* out = (float*)d_out;

    cudaFuncSetAttribute(ihw_prep_t, cudaFuncAttributeMaxDynamicSharedMemorySize, 69632);

    // ---- prep ----
    xprep<<<14336, 256>>>(x, bh + O_XH, bh + O_XL);
    convw_prep<<<10, 256>>>(w11, bh + O_W1H, bh + O_W1L, 4, 32, 80, 1.f / 255.f);
    convw_prep<<<72, 256>>>(w12, bh + O_W2H, bh + O_W2L, 32, 32, 576, 1.f);
    convw_prep<<<144, 256>>>(w21, bh + O_W3H, bh + O_W3L, 32, 64, 576, 1.f);
    convw_prep<<<288, 256>>>(w22, bh + O_W4H, bh + O_W4L, 64, 64, 1152, 1.f);
    convw_prep<<<576, 256>>>(w31, bh + O_W5H, bh + O_W5L, 64, 128, 1152, 1.f);
    convw_prep<<<1152, 256>>>(w32, bh + O_W6H, bh + O_W6L, 128, 128, 2304, 1.f);
    ihw_prep_t<<<dim3(16, 16), 256, 69632>>>(W_ih, bh + O_WIHH, bh + O_WIHL);
    wf_prep<<<1024, 256>>>(Wf, bh + O_WFH, bh + O_WFL);
    perm_hh<<<4096, 256>>>(W_hh, fa + F_WTHH);
    bias_sum<<<8, 256>>>(b_ih, b_hh, fa + F_BG);
    cudaMemcpyAsync(fa + F_H0, h0, 8192 * sizeof(float), cudaMemcpyDeviceToDevice, 0);
    cudaMemcpyAsync(fa + F_C,  c0, 8192 * sizeof(float), cudaMemcpyDeviceToDevice, 0);

    // ---- conv stack ----
    conv_wm2<4, 32, 7, 32, 32, 1><<<24576, 256>>>(
        bh + O_XH, bh + O_XL, bh + O_W1H, bh + O_W1L, b11, bh + O_A1H, bh + O_A1L);
    conv_wm2<32, 32, 6, 32, 32, 2><<<5120, 256>>>(
        bh + O_A1H, bh + O_A1L, bh + O_W2H, bh + O_W2L, b12, bh + O_A2H, bh + O_A2L);
    conv_wm2<32, 64, 5, 16, 16, 1><<<4096, 256>>>(
        bh + O_A2H, bh + O_A2L, bh + O_W3H, bh + O_W3L, b21, bh + O_A3H, bh + O_A3L);
    conv_wm2<64, 64, 4, 16, 16, 2><<<768, 256>>>(
        bh + O_A3H, bh + O_A3L, bh + O_W4H, bh + O_W4L, b22, bh + O_A4H, bh + O_A4L);
    conv_wm2<64, 128, 3, 8, 8, 1><<<1024, 256>>>(
        bh + O_A4H, bh + O_A4L, bh + O_W5H, bh + O_W5L, b31, bh + O_A5H, bh + O_A5L);
    conv_wm2<128, 128, 2, 8, 8, 2><<<128, 256>>>(
        bh + O_A5H, bh + O_A5L, bh + O_W6H, bh + O_W6L, b32, bh + O_FH, bh + O_FL);

    // ---- LSTM input GEMM (512 x 2048 x 2048) ----
    mm_wm2<2048, 2048, false><<<dim3(8, 16), 256>>>(
        bh + O_FH, bh + O_FL, bh + O_WIHH, bh + O_WIHL, fa + F_BG, fa + F_XG);

    // ---- 32 recurrent steps ----
    for (int t = 0; t < 32; t++) {
        float* hin  = fa + ((t & 1) ? F_H1 : F_H0);
        float* hout = fa + ((t & 1) ? F_H0 : F_H1);
        lstm_step<<<64, 128>>>(fa + F_XG, fa + F_WTHH, done, hin, hout,
                               fa + F_C, bh + O_HSH, bh + O_HSL, t);
    }

    // ---- final FC + relu into d_out ----
    mm_wm2<512, 512, true><<<dim3(8, 4), 256>>>(
        bh + O_HSH, bh + O_HSL, bh + O_WFH, bh + O_WFL, bf, out);

    // ---- hT, cT ----
    cudaMemcpyAsync(out + 262144, fa + F_H0, 8192 * sizeof(float),
                    cudaMemcpyDeviceToDevice, 0);
    cudaMemcpyAsync(out + 270336, fa + F_C, 8192 * sizeof(float),
                    cudaMemcpyDeviceToDevice, 0);
}

// round 7
// speedup vs baseline: 1.6492x; 1.5494x over previous
#include <cuda_runtime.h>
#include <cuda_fp16.h>
#include <mma.h>
#include <stdint.h>

using namespace nvcuda;

// ============================================================================
// CNN(6x conv3d) + LSTM(32) + FC.  wmma fp16 2-term: A (fp16) x [Bh + Bl]
// (weights split hi/lo fp16 = 21-bit effective), fp32 accumulate.
// Activations NDHWC single fp16.  Weights k-major.
// ============================================================================

__device__ __forceinline__ void splitw(float v, __half& h, __half& l) {
    h = __float2half_rn(v);
    l = __float2half_rn(v - __half2float(h));
}

// ---- fp16 arena ----
#define O_A1  0LL
#define O_A2  100663296LL
#define O_A3  121634816LL
#define O_A4  155189248LL
#define O_A5  161480704LL
#define O_F   169869312LL
#define O_W1H 170917888LL
#define O_W1L 170920448LL
#define O_W2H 170923008LL
#define O_W2L 170941440LL
#define O_W3H 170959872LL
#define O_W3L 170996736LL
#define O_W4H 171033600LL
#define O_W4L 171107328LL
#define O_W5H 171181056LL
#define O_W5L 171328512LL
#define O_W6H 171475968LL
#define O_W6L 171770880LL
#define O_WIHH 172065792LL
#define O_WIHL 176260096LL
#define O_WFH 180454400LL
#define O_WFL 180716544LL
#define O_X   180978688LL
#define O_HS  195658752LL
#define H_TOTAL 195920896LL
__device__ __half g_hh[H_TOTAL];

// ---- fp32 arena ----
#define F_XG   0LL
#define F_WTHH 1048576LL
#define F_BG   2097152LL
#define F_H0   2099200LL
#define F_H1   2107392LL
#define F_C    2115584LL
#define F_TOTAL 2123776LL
__device__ float g_f[F_TOTAL];

// ---- prep kernels ----
__global__ void xprep(const float* __restrict__ x, __half* __restrict__ xo) {
    long i = ((long)blockIdx.x * blockDim.x + threadIdx.x) * 4;
    float4 v = *(const float4*)(x + i);
    __half2 a = __floats2half2_rn(v.x, v.y);
    __half2 b = __floats2half2_rn(v.z, v.w);
    uint2 p;
    p.x = *reinterpret_cast<uint32_t*>(&a);
    p.y = *reinterpret_cast<uint32_t*>(&b);
    *(uint2*)(xo + i) = p;
}
__global__ void convw_prep(const float* __restrict__ src, __half* __restrict__ dh,
                           __half* __restrict__ dl, int CIN, int COUT, int Kpad, float scale) {
    int i = blockIdx.x * blockDim.x + threadIdx.x;
    if (i >= COUT * Kpad) return;
    int co = i / Kpad, kk = i % Kpad;
    float v = 0.f;
    if (kk < CIN * 18) {
        int cin = kk % CIN, tap = kk / CIN;
        v = src[(co * CIN + cin) * 18 + tap] * scale;
    }
    __half h, l;
    splitw(v, h, l);
    long o = (long)kk * COUT + co;
    dh[o] = h;
    dl[o] = l;
}
// W_ih permute: dst[k2*2048 + n2], k2 = sp*128+c (k = c*16+sp), n2 = u*4+g.
__global__ void ihw_prep_t(const float* __restrict__ src,
                           __half* __restrict__ dh, __half* __restrict__ dl) {
    extern __shared__ __half ts[];                  // [2][128][136]
    __half* TH = ts;
    __half* TL = ts + 128 * 136;
    int tid = threadIdx.x;
    int kb = blockIdx.x * 128, nbv = blockIdx.y * 128;
    {
        int n2 = nbv + (tid >> 1);
        int g = n2 & 3, u = n2 >> 2;
        const float* srow = src + (long)(g * 512 + u) * 2048 + kb + (tid & 1) * 64;
        int klo = (tid & 1) * 64, col = tid >> 1;
#pragma unroll
        for (int q = 0; q < 16; q++) {
            float4 v = *(const float4*)(srow + q * 4);
            float vv[4] = {v.x, v.y, v.z, v.w};
#pragma unroll
            for (int e = 0; e < 4; e++) {
                __half h, l;
                splitw(vv[e], h, l);
                TH[(klo + q * 4 + e) * 136 + col] = h;
                TL[(klo + q * 4 + e) * 136 + col] = l;
            }
        }
    }
    __syncthreads();
    {
        int kl = tid >> 1, nh = (tid & 1) * 64;
        int cl = kl >> 4, sp = kl & 15;
        int k2 = sp * 128 + (kb >> 4) + cl;
        long base = (long)k2 * 2048 + nbv + nh;
#pragma unroll
        for (int q = 0; q < 8; q++) {
            *(uint4*)(dh + base + q * 8) = *(const uint4*)(TH + kl * 136 + nh + q * 8);
            *(uint4*)(dl + base + q * 8) = *(const uint4*)(TL + kl * 136 + nh + q * 8);
        }
    }
}
__global__ void wf_prep(const float* __restrict__ src, __half* __restrict__ dh,
                        __half* __restrict__ dl) {
    int i = blockIdx.x * blockDim.x + threadIdx.x;
    if (i >= 512 * 512) return;
    int n = i >> 9, k = i & 511;
    __half h, l;
    splitw(src[i], h, l);
    long o = (long)k * 512 + n;
    dh[o] = h;
    dl[o] = l;
}
__global__ void perm_hh(const float* __restrict__ src, float* __restrict__ dst) {
    int i = blockIdx.x * blockDim.x + threadIdx.x;
    if (i < 2048 * 512) {
        int r = i >> 9, k = i & 511;
        int g = r >> 9, u = r & 511;
        dst[k * 2048 + (u << 2) + g] = src[i];
    }
}
__global__ void bias_sum(const float* __restrict__ bi, const float* __restrict__ bh2,
                         float* __restrict__ dst) {
    int i = blockIdx.x * blockDim.x + threadIdx.x;
    if (i < 2048) {
        int g = i >> 9, u = i & 511;
        dst[(u << 2) + g] = bi[i] + bh2[i];
    }
}

// ============================================================================
// wmma implicit-GEMM conv, fp16 2-term.  CTA: BM x COUT, BK=16, reg prefetch.
// ============================================================================
template <int CIN, int COUT, int DIN, int HIN, int WIN, int S>
__global__ __launch_bounds__(256) void conv_wm3(
    const __half* __restrict__ ain,
    const __half* __restrict__ whi, const __half* __restrict__ wlo,
    const float* __restrict__ bias, __half* __restrict__ aout) {
    constexpr int DOUT = DIN - 1;
    constexpr int HOUT = (S == 1) ? HIN : HIN / 2;
    constexpr int WOUT = (S == 1) ? WIN : WIN / 2;
    constexpr int Kpad = (CIN == 4) ? 80 : CIN * 18;
    constexpr int NC = Kpad / 16;
    constexpr int BM = (COUT >= 128) ? 64 : 128;
    constexpr int TPR = 256 / BM;
    constexpr int HS = 16 / TPR;
    constexpr int WN = (COUT >= 128) ? 4 : (COUT / 32);
    constexpr int WM = 8 / WN, MF = BM / (WM * 16);
    constexpr int LDA = 24, LDB = COUT + 8, LDC = COUT + 4;
    constexpr int ASZ = BM * LDA, BSZ = 16 * LDB;
    constexpr int L2C = (CIN == 32) ? 5 : ((CIN == 64) ? 6 : 7);
    constexpr int LOADSZ = (ASZ + 2 * BSZ) * 2;
    constexpr int CSZ = BM * LDC * 4;
    constexpr int SMSZ = (LOADSZ > CSZ) ? LOADSZ : CSZ;

    __shared__ __align__(16) char sm[SMSZ];
    __half* As = (__half*)sm;
    __half* BsH = As + ASZ;
    __half* BsL = BsH + BSZ;
    float* Cs = (float*)sm;

    int tid = threadIdx.x, wid = tid >> 5;
    int m0 = blockIdx.x * BM;
    int r = tid / TPR;
    int h = (tid % TPR) * HS;
    int m = m0 + r;
    int ow = m % WOUT; int t1 = m / WOUT;
    int oh = t1 % HOUT; int t2 = t1 / HOUT;
    int od = t2 % DOUT; int bb = t2 / DOUT;

    constexpr int TPK = COUT / 8;
    int kb = tid / TPK, nb = (tid % TPK) * 8;
    bool bact = kb < 16;

    auto lda_r = [&](int c, uint4& va) {
        va = make_uint4(0u, 0u, 0u, 0u);
        if constexpr (CIN == 4) {
            int kk = c * 16 + h;
#pragma unroll
            for (int t = 0; t < 2; t++) {
                int tap = kk / 4 + t;
                if (tap < 18) {
                    int kd = (tap >= 9) ? 1 : 0; int rr = tap - 9 * kd;
                    int kh = rr / 3, kw = rr - 3 * kh;
                    int ih = oh - 1 + kh, iw = ow - 1 + kw;
                    if ((unsigned)ih < (unsigned)HIN && (unsigned)iw < (unsigned)WIN) {
                        long g = ((((long)bb * DIN + od + kd) * HIN + ih) * WIN + iw) * 4;
                        uint2 xh = *(const uint2*)(ain + g);
                        if (t == 0) { va.x = xh.x; va.y = xh.y; }
                        else        { va.z = xh.x; va.w = xh.y; }
                    }
                }
            }
        } else {
            int kk = c * 16 + h;
            int tap = kk >> L2C, cin = kk & (CIN - 1);
            int kd = (tap >= 9) ? 1 : 0; int rr = tap - 9 * kd;
            int kh = rr / 3, kw = rr - 3 * kh;
            int ih = oh * S - 1 + kh, iw = ow * S - 1 + kw;
            if ((unsigned)ih < (unsigned)HIN && (unsigned)iw < (unsigned)WIN) {
                long g = ((((long)bb * DIN + od + kd) * HIN + ih) * WIN + iw) * CIN + cin;
                if constexpr (TPR == 2) {
                    va = *(const uint4*)(ain + g);
                } else {
                    uint2 xh = *(const uint2*)(ain + g);
                    va.x = xh.x; va.y = xh.y;
                }
            }
        }
    };
    auto ldb_r = [&](int c, uint4& wh, uint4& wl) {
        if (bact) {
            long g = (long)(c * 16 + kb) * COUT + nb;
            wh = *(const uint4*)(whi + g);
            wl = *(const uint4*)(wlo + g);
        }
    };

    int wm = wid / WN, wn = wid % WN;
    wmma::fragment<wmma::accumulator, 16, 16, 16, float> acc[MF][2];
#pragma unroll
    for (int i = 0; i < MF; i++)
#pragma unroll
        for (int j = 0; j < 2; j++) wmma::fill_fragment(acc[i][j], 0.f);

    uint4 va = make_uint4(0,0,0,0), wh = va, wl = va;
    uint4 nva = va, nwh = va, nwl = va;
    lda_r(0, va); ldb_r(0, wh, wl);
    for (int c = 0; c < NC; c++) {
        __syncthreads();
        if constexpr (TPR == 2) {
            *(uint4*)(As + r * LDA + h) = va;
        } else {
            *(uint2*)(As + r * LDA + h) = make_uint2(va.x, va.y);
        }
        if (bact) {
            *(uint4*)(BsH + kb * LDB + nb) = wh;
            *(uint4*)(BsL + kb * LDB + nb) = wl;
        }
        if (c + 1 < NC) { lda_r(c + 1, nva); ldb_r(c + 1, nwh, nwl); }
        __syncthreads();
        wmma::fragment<wmma::matrix_b, 16, 16, 16, __half, wmma::row_major> fbh[2], fbl[2];
#pragma unroll
        for (int j = 0; j < 2; j++) {
            wmma::load_matrix_sync(fbh[j], BsH + wn * 32 + j * 16, LDB);
            wmma::load_matrix_sync(fbl[j], BsL + wn * 32 + j * 16, LDB);
        }
#pragma unroll
        for (int i = 0; i < MF; i++) {
            wmma::fragment<wmma::matrix_a, 16, 16, 16, __half, wmma::row_major> fa;
            wmma::load_matrix_sync(fa, As + ((wm * MF + i) * 16) * LDA, LDA);
#pragma unroll
            for (int j = 0; j < 2; j++) {
                wmma::mma_sync(acc[i][j], fa, fbh[j], acc[i][j]);
                wmma::mma_sync(acc[i][j], fa, fbl[j], acc[i][j]);
            }
        }
        va = nva; wh = nwh; wl = nwl;
    }
    __syncthreads();
#pragma unroll
    for (int i = 0; i < MF; i++)
#pragma unroll
        for (int j = 0; j < 2; j++)
            wmma::store_matrix_sync(Cs + ((wm * MF + i) * 16) * LDC + wn * 32 + j * 16,
                                    acc[i][j], LDC, wmma::mem_row_major);
    __syncthreads();
    {
        int r2 = tid / TPR, ch0 = (tid % TPR) * (COUT / TPR);
        long base = (long)(m0 + r2) * COUT + ch0;
#pragma unroll
        for (int c = 0; c < COUT / TPR; c += 4) {
            float v0 = fmaxf(Cs[r2 * LDC + ch0 + c]     + bias[ch0 + c], 0.f);
            float v1 = fmaxf(Cs[r2 * LDC + ch0 + c + 1] + bias[ch0 + c + 1], 0.f);
            float v2 = fmaxf(Cs[r2 * LDC + ch0 + c + 2] + bias[ch0 + c + 2], 0.f);
            float v3 = fmaxf(Cs[r2 * LDC + ch0 + c + 3] + bias[ch0 + c + 3], 0.f);
            __half2 p0 = __floats2half2_rn(v0, v1);
            __half2 p1 = __floats2half2_rn(v2, v3);
            uint2 p;
            p.x = *reinterpret_cast<uint32_t*>(&p0);
            p.y = *reinterpret_cast<uint32_t*>(&p1);
            *(uint2*)(aout + base + c) = p;
        }
    }
}

// ============================================================================
// wmma GEMM fp16 2-term, fp32 out.  CTA: 64 x 128, BK=16.
// ============================================================================
template <int NTOT, int K, bool RELU>
__global__ __launch_bounds__(256) void mm_wm3(
    const __half* __restrict__ ain,
    const __half* __restrict__ whi, const __half* __restrict__ wlo,
    const float* __restrict__ bias, float* __restrict__ out) {
    constexpr int NC = K / 16;
    constexpr int LDA = 24, LDB = 136, LDC = 132;
    constexpr int ASZ = 64 * LDA, BSZ = 16 * LDB;
    constexpr int LOADSZ = (ASZ + 2 * BSZ) * 2;
    constexpr int CSZ = 64 * LDC * 4;
    constexpr int SMSZ = (LOADSZ > CSZ) ? LOADSZ : CSZ;

    __shared__ __align__(16) char sm[SMSZ];
    __half* As = (__half*)sm;
    __half* BsH = As + ASZ;
    __half* BsL = BsH + BSZ;
    float* Cs = (float*)sm;

    int tid = threadIdx.x, wid = tid >> 5;
    int m0 = blockIdx.x * 64, n0 = blockIdx.y * 128;
    int r = tid >> 2, h = (tid & 3) * 4;
    long mrow = m0 + r;
    int kb = tid >> 4, nb = (tid & 15) * 8;

    auto lda_r = [&](int c, uint2& va) {
        va = *(const uint2*)(ain + mrow * K + c * 16 + h);
    };
    auto ldb_r = [&](int c, uint4& wh, uint4& wl) {
        long g = (long)(c * 16 + kb) * NTOT + n0 + nb;
        wh = *(const uint4*)(whi + g);
        wl = *(const uint4*)(wlo + g);
    };

    int wm = wid >> 2, wn = wid & 3;
    wmma::fragment<wmma::accumulator, 16, 16, 16, float> acc[2][2];
#pragma unroll
    for (int i = 0; i < 2; i++)
#pragma unroll
        for (int j = 0; j < 2; j++) wmma::fill_fragment(acc[i][j], 0.f);

    uint2 va, nva = make_uint2(0,0);
    uint4 wh, wl, nwh = make_uint4(0,0,0,0), nwl = nwh;
    lda_r(0, va); ldb_r(0, wh, wl);
    for (int c = 0; c < NC; c++) {
        __syncthreads();
        *(uint2*)(As + r * LDA + h) = va;
        *(uint4*)(BsH + kb * LDB + nb) = wh;
        *(uint4*)(BsL + kb * LDB + nb) = wl;
        if (c + 1 < NC) { lda_r(c + 1, nva); ldb_r(c + 1, nwh, nwl); }
        __syncthreads();
        wmma::fragment<wmma::matrix_b, 16, 16, 16, __half, wmma::row_major> fbh[2], fbl[2];
#pragma unroll
        for (int j = 0; j < 2; j++) {
            wmma::load_matrix_sync(fbh[j], BsH + wn * 32 + j * 16, LDB);
            wmma::load_matrix_sync(fbl[j], BsL + wn * 32 + j * 16, LDB);
        }
#pragma unroll
        for (int i = 0; i < 2; i++) {
            wmma::fragment<wmma::matrix_a, 16, 16, 16, __half, wmma::row_major> fa;
            wmma::load_matrix_sync(fa, As + ((wm * 2 + i) * 16) * LDA, LDA);
#pragma unroll
            for (int j = 0; j < 2; j++) {
                wmma::mma_sync(acc[i][j], fa, fbh[j], acc[i][j]);
                wmma::mma_sync(acc[i][j], fa, fbl[j], acc[i][j]);
            }
        }
        va = nva; wh = nwh; wl = nwl;
    }
    __syncthreads();
#pragma unroll
    for (int i = 0; i < 2; i++)
#pragma unroll
        for (int j = 0; j < 2; j++)
            wmma::store_matrix_sync(Cs + ((wm * 2 + i) * 16) * LDC + wn * 32 + j * 16,
                                    acc[i][j], LDC, wmma::mem_row_major);
    __syncthreads();
    {
        int r2 = tid >> 2, ch0 = (tid & 3) * 32;
        long base = (long)(m0 + r2) * NTOT + n0 + ch0;
#pragma unroll
        for (int c = 0; c < 32; c += 4) {
            float4 v;
            v.x = Cs[r2 * LDC + ch0 + c]     + bias[n0 + ch0 + c];
            v.y = Cs[r2 * LDC + ch0 + c + 1] + bias[n0 + ch0 + c + 1];
            v.z = Cs[r2 * LDC + ch0 + c + 2] + bias[n0 + ch0 + c + 2];
            v.w = Cs[r2 * LDC + ch0 + c + 3] + bias[n0 + ch0 + c + 3];
            if (RELU) {
                v.x = fmaxf(v.x, 0.f); v.y = fmaxf(v.y, 0.f);
                v.z = fmaxf(v.z, 0.f); v.w = fmaxf(v.w, 0.f);
            }
            *(float4*)(out + base + c) = v;
        }
    }
}

// ---- LSTM recurrent step (fp32), emits hs as fp16 ----
__global__ void lstm_step(const float* __restrict__ xg, const float* __restrict__ wthh,
                          const float* __restrict__ done, const float* __restrict__ h_in,
                          float* __restrict__ h_out, float* __restrict__ c,
                          __half* __restrict__ hs, int t) {
    constexpr int PAD = 520;
    __shared__ __align__(16) float sh_h[16 * PAD];
    __shared__ __align__(16) float Bs[16][32];
    int tid = threadIdx.x;
    int n0 = blockIdx.x * 32;
#pragma unroll
    for (int i = 0; i < 16; i++) {
        int idx4 = i * 128 + tid;
        int b = idx4 >> 7;
        int qq = idx4 & 127;
        float keep = 1.f - done[t * 16 + b];
        float4 v = ((const float4*)h_in)[idx4];
        v.x *= keep; v.y *= keep; v.z *= keep; v.w *= keep;
        ((float4*)sh_h)[b * (PAD / 4) + qq] = v;
    }
    __syncthreads();
    int tx = tid & 7, ty = tid >> 3;
    float acc[4] = {0.f, 0.f, 0.f, 0.f};
    for (int k0 = 0; k0 < 512; k0 += 16) {
        {
            int kl = tid >> 3, nl = (tid & 7) * 4;
            *(float4*)&Bs[kl][nl] = *(const float4*)&wthh[(k0 + kl) * 2048 + n0 + nl];
        }
        __syncthreads();
#pragma unroll
        for (int kk = 0; kk < 16; kk++) {
            float a = sh_h[ty * PAD + k0 + kk];
            float4 b4 = *(const float4*)&Bs[kk][tx * 4];
            acc[0] += a * b4.x; acc[1] += a * b4.y;
            acc[2] += a * b4.z; acc[3] += a * b4.w;
        }
        __syncthreads();
    }
    int b = ty;
    int u = (n0 >> 2) + tx;
    float4 xv = *(const float4*)&xg[(t * 16 + b) * 2048 + n0 + tx * 4];
    float ig = acc[0] + xv.x, fg = acc[1] + xv.y, gg = acc[2] + xv.z, og = acc[3] + xv.w;
    float keep = 1.f - done[t * 16 + b];
    float cold = c[b * 512 + u] * keep;
    float si = 1.f / (1.f + expf(-ig));
    float sf = 1.f / (1.f + expf(-fg));
    float so = 1.f / (1.f + expf(-og));
    float cn = sf * cold + si * tanhf(gg);
    float hn = so * tanhf(cn);
    c[b * 512 + u] = cn;
    h_out[b * 512 + u] = hn;
    hs[(long)(t * 16 + b) * 512 + u] = __float2half_rn(hn);
}

// ---------------------------------------------------------------------------
extern "C" void kernel_launch(void* const* d_in, const int* in_sizes, int n_in,
                              void* d_out, int out_size) {
    (void)in_sizes; (void)n_in; (void)out_size;
    __half* hh = nullptr;
    float* fa = nullptr;
    cudaGetSymbolAddress((void**)&hh, g_hh);
    cudaGetSymbolAddress((void**)&fa, g_f);

    const float* x    = (const float*)d_in[0];
    const float* done = (const float*)d_in[1];
    const float* h0   = (const float*)d_in[2];
    const float* c0   = (const float*)d_in[3];
    const float* w11  = (const float*)d_in[4];
    const float* b11  = (const float*)d_in[5];
    const float* w12  = (const float*)d_in[6];
    const float* b12  = (const float*)d_in[7];
    const float* w21  = (const float*)d_in[8];
    const float* b21  = (const float*)d_in[9];
    const float* w22  = (const float*)d_in[10];
    const float* b22  = (const float*)d_in[11];
    const float* w31  = (const float*)d_in[12];
    const float* b31  = (const float*)d_in[13];
    const float* w32  = (const float*)d_in[14];
    const float* b32  = (const float*)d_in[15];
    const float* W_ih = (const float*)d_in[16];
    const float* W_hh = (const float*)d_in[17];
    const float* b_ih = (const float*)d_in[18];
    const float* b_hh = (const float*)d_in[19];
    const float* Wf   = (const float*)d_in[20];
    const float* bf   = (const float*)d_in[21];
    float* out = (float*)d_out;

    cudaFuncSetAttribute(ihw_prep_t, cudaFuncAttributeMaxDynamicSharedMemorySize, 69632);

    // ---- prep ----
    xprep<<<14336, 256>>>(x, hh + O_X);
    convw_prep<<<10, 256>>>(w11, hh + O_W1H, hh + O_W1L, 4, 32, 80, 1.f / 255.f);
    convw_prep<<<72, 256>>>(w12, hh + O_W2H, hh + O_W2L, 32, 32, 576, 1.f);
    convw_prep<<<144, 256>>>(w21, hh + O_W3H, hh + O_W3L, 32, 64, 576, 1.f);
    convw_prep<<<288, 256>>>(w22, hh + O_W4H, hh + O_W4L, 64, 64, 1152, 1.f);
    convw_prep<<<576, 256>>>(w31, hh + O_W5H, hh + O_W5L, 64, 128, 1152, 1.f);
    convw_prep<<<1152, 256>>>(w32, hh + O_W6H, hh + O_W6L, 128, 128, 2304, 1.f);
    ihw_prep_t<<<dim3(16, 16), 256, 69632>>>(W_ih, hh + O_WIHH, hh + O_WIHL);
    wf_prep<<<1024, 256>>>(Wf, hh + O_WFH, hh + O_WFL);
    perm_hh<<<4096, 256>>>(W_hh, fa + F_WTHH);
    bias_sum<<<8, 256>>>(b_ih, b_hh, fa + F_BG);
    cudaMemcpyAsync(fa + F_H0, h0, 8192 * sizeof(float), cudaMemcpyDeviceToDevice, 0);
    cudaMemcpyAsync(fa + F_C,  c0, 8192 * sizeof(float), cudaMemcpyDeviceToDevice, 0);

    // ---- conv stack ----
    conv_wm3<4, 32, 7, 32, 32, 1><<<24576, 256>>>(
        hh + O_X, hh + O_W1H, hh + O_W1L, b11, hh + O_A1);
    conv_wm3<32, 32, 6, 32, 32, 2><<<5120, 256>>>(
        hh + O_A1, hh + O_W2H, hh + O_W2L, b12, hh + O_A2);
    conv_wm3<32, 64, 5, 16, 16, 1><<<4096, 256>>>(
        hh + O_A2, hh + O_W3H, hh + O_W3L, b21, hh + O_A3);
    conv_wm3<64, 64, 4, 16, 16, 2><<<768, 256>>>(
        hh + O_A3, hh + O_W4H, hh + O_W4L, b22, hh + O_A4);
    conv_wm3<64, 128, 3, 8, 8, 1><<<1024, 256>>>(
        hh + O_A4, hh + O_W5H, hh + O_W5L, b31, hh + O_A5);
    conv_wm3<128, 128, 2, 8, 8, 2><<<128, 256>>>(
        hh + O_A5, hh + O_W6H, hh + O_W6L, b32, hh + O_F);

    // ---- LSTM input GEMM (512 x 2048 x 2048) ----
    mm_wm3<2048, 2048, false><<<dim3(8, 16), 256>>>(
        hh + O_F, hh + O_WIHH, hh + O_WIHL, fa + F_BG, fa + F_XG);

    // ---- 32 recurrent steps ----
    for (int t = 0; t < 32; t++) {
        float* hin  = fa + ((t & 1) ? F_H1 : F_H0);
        float* hout = fa + ((t & 1) ? F_H0 : F_H1);
        lstm_step<<<64, 128>>>(fa + F_XG, fa + F_WTHH, done, hin, hout,
                               fa + F_C, hh + O_HS, t);
    }

    // ---- final FC + relu into d_out ----
    mm_wm3<512, 512, true><<<dim3(8, 4), 256>>>(
        hh + O_HS, hh + O_WFH, hh + O_WFL, bf, out);

    // ---- hT, cT ----
    cudaMemcpyAsync(out + 262144, fa + F_H0, 8192 * sizeof(float),
                    cudaMemcpyDeviceToDevice, 0);
    cudaMemcpyAsync(out + 270336, fa + F_C, 8192 * sizeof(float),
                    cudaMemcpyDeviceToDevice, 0);
}

// round 8
// speedup vs baseline: 1.9481x; 1.1812x over previous
#include <cuda_runtime.h>
#include <cuda_fp16.h>
#include <mma.h>
#include <stdint.h>

using namespace nvcuda;

// ============================================================================
// CNN(6x conv3d) + LSTM(32) + FC.
// Conv layers: wmma fp16 single-term (A fp16 x W fp16), fp32 accumulate.
// IH/FC GEMMs: fp16 2-term (W split hi/lo = 21-bit effective).
// Activations NDHWC fp16.  Weights k-major.
// ============================================================================

__device__ __forceinline__ void splitw(float v, __half& h, __half& l) {
    h = __float2half_rn(v);
    l = __float2half_rn(v - __half2float(h));
}

// ---- fp16 arena ----
#define O_A1  0LL
#define O_A2  100663296LL
#define O_A3  121634816LL
#define O_A4  155189248LL
#define O_A5  161480704LL
#define O_F   169869312LL
#define O_W1  170917888LL
#define O_W2  170923008LL
#define O_W3  170959872LL
#define O_W4  171033600LL
#define O_W5  171181056LL
#define O_W6  171475968LL
#define O_WIHH 172065792LL
#define O_WIHL 176260096LL
#define O_WFH 180454400LL
#define O_WFL 180716544LL
#define O_X   180978688LL
#define O_HS  195658752LL
#define H_TOTAL 195920896LL
__device__ __half g_hh[H_TOTAL];

// ---- fp32 arena ----
#define F_XG   0LL
#define F_WTHH 1048576LL
#define F_BG   2097152LL
#define F_H0   2099200LL
#define F_H1   2107392LL
#define F_C    2115584LL
#define F_TOTAL 2123776LL
__device__ float g_f[F_TOTAL];

// ---- prep kernels ----
__global__ void xprep(const float* __restrict__ x, __half* __restrict__ xo) {
    long i = ((long)blockIdx.x * blockDim.x + threadIdx.x) * 4;
    float4 v = *(const float4*)(x + i);
    __half2 a = __floats2half2_rn(v.x, v.y);
    __half2 b = __floats2half2_rn(v.z, v.w);
    uint2 p;
    p.x = *reinterpret_cast<uint32_t*>(&a);
    p.y = *reinterpret_cast<uint32_t*>(&b);
    *(uint2*)(xo + i) = p;
}
__global__ void convw_prep(const float* __restrict__ src, __half* __restrict__ dw,
                           int CIN, int COUT, int Kpad, float scale) {
    int i = blockIdx.x * blockDim.x + threadIdx.x;
    if (i >= COUT * Kpad) return;
    int co = i / Kpad, kk = i % Kpad;
    float v = 0.f;
    if (kk < CIN * 18) {
        int cin = kk % CIN, tap = kk / CIN;
        v = src[(co * CIN + cin) * 18 + tap] * scale;
    }
    dw[(long)kk * COUT + co] = __float2half_rn(v);
}
// W_ih permute: dst[k2*2048 + n2], k2 = sp*128+c (k = c*16+sp), n2 = u*4+g.
__global__ void ihw_prep_t(const float* __restrict__ src,
                           __half* __restrict__ dh, __half* __restrict__ dl) {
    extern __shared__ __half ts[];                  // [2][128][136]
    __half* TH = ts;
    __half* TL = ts + 128 * 136;
    int tid = threadIdx.x;
    int kb = blockIdx.x * 128, nbv = blockIdx.y * 128;
    {
        int n2 = nbv + (tid >> 1);
        int g = n2 & 3, u = n2 >> 2;
        const float* srow = src + (long)(g * 512 + u) * 2048 + kb + (tid & 1) * 64;
        int klo = (tid & 1) * 64, col = tid >> 1;
#pragma unroll
        for (int q = 0; q < 16; q++) {
            float4 v = *(const float4*)(srow + q * 4);
            float vv[4] = {v.x, v.y, v.z, v.w};
#pragma unroll
            for (int e = 0; e < 4; e++) {
                __half h, l;
                splitw(vv[e], h, l);
                TH[(klo + q * 4 + e) * 136 + col] = h;
                TL[(klo + q * 4 + e) * 136 + col] = l;
            }
        }
    }
    __syncthreads();
    {
        int kl = tid >> 1, nh = (tid & 1) * 64;
        int cl = kl >> 4, sp = kl & 15;
        int k2 = sp * 128 + (kb >> 4) + cl;
        long base = (long)k2 * 2048 + nbv + nh;
#pragma unroll
        for (int q = 0; q < 8; q++) {
            *(uint4*)(dh + base + q * 8) = *(const uint4*)(TH + kl * 136 + nh + q * 8);
            *(uint4*)(dl + base + q * 8) = *(const uint4*)(TL + kl * 136 + nh + q * 8);
        }
    }
}
__global__ void wf_prep(const float* __restrict__ src, __half* __restrict__ dh,
                        __half* __restrict__ dl) {
    int i = blockIdx.x * blockDim.x + threadIdx.x;
    if (i >= 512 * 512) return;
    int n = i >> 9, k = i & 511;
    __half h, l;
    splitw(src[i], h, l);
    long o = (long)k * 512 + n;
    dh[o] = h;
    dl[o] = l;
}
__global__ void perm_hh(const float* __restrict__ src, float* __restrict__ dst) {
    int i = blockIdx.x * blockDim.x + threadIdx.x;
    if (i < 2048 * 512) {
        int r = i >> 9, k = i & 511;
        int g = r >> 9, u = r & 511;
        dst[k * 2048 + (u << 2) + g] = src[i];
    }
}
__global__ void bias_sum(const float* __restrict__ bi, const float* __restrict__ bh2,
                         float* __restrict__ dst) {
    int i = blockIdx.x * blockDim.x + threadIdx.x;
    if (i < 2048) {
        int g = i >> 9, u = i & 511;
        dst[(u << 2) + g] = bi[i] + bh2[i];
    }
}

// ============================================================================
// wmma implicit-GEMM conv, fp16 single-term.  CTA: BM x COUT, BK=16.
// ============================================================================
template <int CIN, int COUT, int DIN, int HIN, int WIN, int S>
__global__ __launch_bounds__(256) void conv_wm4(
    const __half* __restrict__ ain, const __half* __restrict__ wgt,
    const float* __restrict__ bias, __half* __restrict__ aout) {
    constexpr int DOUT = DIN - 1;
    constexpr int HOUT = (S == 1) ? HIN : HIN / 2;
    constexpr int WOUT = (S == 1) ? WIN : WIN / 2;
    constexpr int Kpad = (CIN == 4) ? 80 : CIN * 18;
    constexpr int NC = Kpad / 16;
    constexpr int BM = (COUT >= 128) ? 64 : 128;
    constexpr int TPR = 256 / BM;
    constexpr int HS = 16 / TPR;
    constexpr int WN = (COUT >= 128) ? 4 : (COUT / 32);
    constexpr int WM = 8 / WN, MF = BM / (WM * 16);
    constexpr int LDA = 24, LDB = COUT + 8, LDC = COUT + 4;
    constexpr int ASZ = BM * LDA, BSZ = 16 * LDB;
    constexpr int L2C = (CIN == 32) ? 5 : ((CIN == 64) ? 6 : 7);
    constexpr int LOADSZ = (ASZ + BSZ) * 2;
    constexpr int CSZ = BM * LDC * 4;
    constexpr int SMSZ = (LOADSZ > CSZ) ? LOADSZ : CSZ;

    __shared__ __align__(16) char sm[SMSZ];
    __half* As = (__half*)sm;
    __half* Bs = As + ASZ;
    float* Cs = (float*)sm;

    int tid = threadIdx.x, wid = tid >> 5;
    int m0 = blockIdx.x * BM;
    int r = tid / TPR;
    int h = (tid % TPR) * HS;
    int m = m0 + r;
    int ow = m % WOUT; int t1 = m / WOUT;
    int oh = t1 % HOUT; int t2 = t1 / HOUT;
    int od = t2 % DOUT; int bb = t2 / DOUT;

    constexpr int TPK = COUT / 8;
    int kb = tid / TPK, nb = (tid % TPK) * 8;
    bool bact = kb < 16;

    auto lda_r = [&](int c, uint4& va) {
        va = make_uint4(0u, 0u, 0u, 0u);
        if constexpr (CIN == 4) {
            int kk = c * 16 + h;
#pragma unroll
            for (int t = 0; t < 2; t++) {
                int tap = kk / 4 + t;
                if (tap < 18) {
                    int kd = (tap >= 9) ? 1 : 0; int rr = tap - 9 * kd;
                    int kh = rr / 3, kw = rr - 3 * kh;
                    int ih = oh - 1 + kh, iw = ow - 1 + kw;
                    if ((unsigned)ih < (unsigned)HIN && (unsigned)iw < (unsigned)WIN) {
                        long g = ((((long)bb * DIN + od + kd) * HIN + ih) * WIN + iw) * 4;
                        uint2 xh = *(const uint2*)(ain + g);
                        if (t == 0) { va.x = xh.x; va.y = xh.y; }
                        else        { va.z = xh.x; va.w = xh.y; }
                    }
                }
            }
        } else {
            int kk = c * 16 + h;
            int tap = kk >> L2C, cin = kk & (CIN - 1);
            int kd = (tap >= 9) ? 1 : 0; int rr = tap - 9 * kd;
            int kh = rr / 3, kw = rr - 3 * kh;
            int ih = oh * S - 1 + kh, iw = ow * S - 1 + kw;
            if ((unsigned)ih < (unsigned)HIN && (unsigned)iw < (unsigned)WIN) {
                long g = ((((long)bb * DIN + od + kd) * HIN + ih) * WIN + iw) * CIN + cin;
                if constexpr (TPR == 2) {
                    va = *(const uint4*)(ain + g);
                } else {
                    uint2 xh = *(const uint2*)(ain + g);
                    va.x = xh.x; va.y = xh.y;
                }
            }
        }
    };
    auto ldb_r = [&](int c, uint4& wv) {
        if (bact) {
            wv = *(const uint4*)(wgt + (long)(c * 16 + kb) * COUT + nb);
        }
    };

    int wm = wid / WN, wn = wid % WN;
    wmma::fragment<wmma::accumulator, 16, 16, 16, float> acc[MF][2];
#pragma unroll
    for (int i = 0; i < MF; i++)
#pragma unroll
        for (int j = 0; j < 2; j++) wmma::fill_fragment(acc[i][j], 0.f);

    uint4 va = make_uint4(0,0,0,0), wv = va, nva = va, nwv = va;
    lda_r(0, va); ldb_r(0, wv);
    for (int c = 0; c < NC; c++) {
        __syncthreads();
        if constexpr (TPR == 2) {
            *(uint4*)(As + r * LDA + h) = va;
        } else {
            *(uint2*)(As + r * LDA + h) = make_uint2(va.x, va.y);
        }
        if (bact) {
            *(uint4*)(Bs + kb * LDB + nb) = wv;
        }
        if (c + 1 < NC) { lda_r(c + 1, nva); ldb_r(c + 1, nwv); }
        __syncthreads();
        wmma::fragment<wmma::matrix_b, 16, 16, 16, __half, wmma::row_major> fb[2];
#pragma unroll
        for (int j = 0; j < 2; j++)
            wmma::load_matrix_sync(fb[j], Bs + wn * 32 + j * 16, LDB);
#pragma unroll
        for (int i = 0; i < MF; i++) {
            wmma::fragment<wmma::matrix_a, 16, 16, 16, __half, wmma::row_major> fa;
            wmma::load_matrix_sync(fa, As + ((wm * MF + i) * 16) * LDA, LDA);
#pragma unroll
            for (int j = 0; j < 2; j++)
                wmma::mma_sync(acc[i][j], fa, fb[j], acc[i][j]);
        }
        va = nva; wv = nwv;
    }
    __syncthreads();
#pragma unroll
    for (int i = 0; i < MF; i++)
#pragma unroll
        for (int j = 0; j < 2; j++)
            wmma::store_matrix_sync(Cs + ((wm * MF + i) * 16) * LDC + wn * 32 + j * 16,
                                    acc[i][j], LDC, wmma::mem_row_major);
    __syncthreads();
    {
        int r2 = tid / TPR, ch0 = (tid % TPR) * (COUT / TPR);
        long base = (long)(m0 + r2) * COUT + ch0;
#pragma unroll
        for (int c = 0; c < COUT / TPR; c += 4) {
            float v0 = fmaxf(Cs[r2 * LDC + ch0 + c]     + bias[ch0 + c], 0.f);
            float v1 = fmaxf(Cs[r2 * LDC + ch0 + c + 1] + bias[ch0 + c + 1], 0.f);
            float v2 = fmaxf(Cs[r2 * LDC + ch0 + c + 2] + bias[ch0 + c + 2], 0.f);
            float v3 = fmaxf(Cs[r2 * LDC + ch0 + c + 3] + bias[ch0 + c + 3], 0.f);
            __half2 p0 = __floats2half2_rn(v0, v1);
            __half2 p1 = __floats2half2_rn(v2, v3);
            uint2 p;
            p.x = *reinterpret_cast<uint32_t*>(&p0);
            p.y = *reinterpret_cast<uint32_t*>(&p1);
            *(uint2*)(aout + base + c) = p;
        }
    }
}

// ============================================================================
// wmma GEMM fp16 2-term (weights 21-bit), fp32 out.  CTA: 64 x 128, BK=16.
// ============================================================================
template <int NTOT, int K, bool RELU>
__global__ __launch_bounds__(256) void mm_wm3(
    const __half* __restrict__ ain,
    const __half* __restrict__ whi, const __half* __restrict__ wlo,
    const float* __restrict__ bias, float* __restrict__ out) {
    constexpr int NC = K / 16;
    constexpr int LDA = 24, LDB = 136, LDC = 132;
    constexpr int ASZ = 64 * LDA, BSZ = 16 * LDB;
    constexpr int LOADSZ = (ASZ + 2 * BSZ) * 2;
    constexpr int CSZ = 64 * LDC * 4;
    constexpr int SMSZ = (LOADSZ > CSZ) ? LOADSZ : CSZ;

    __shared__ __align__(16) char sm[SMSZ];
    __half* As = (__half*)sm;
    __half* BsH = As + ASZ;
    __half* BsL = BsH + BSZ;
    float* Cs = (float*)sm;

    int tid = threadIdx.x, wid = tid >> 5;
    int m0 = blockIdx.x * 64, n0 = blockIdx.y * 128;
    int r = tid >> 2, h = (tid & 3) * 4;
    long mrow = m0 + r;
    int kb = tid >> 4, nb = (tid & 15) * 8;

    auto lda_r = [&](int c, uint2& va) {
        va = *(const uint2*)(ain + mrow * K + c * 16 + h);
    };
    auto ldb_r = [&](int c, uint4& wh, uint4& wl) {
        long g = (long)(c * 16 + kb) * NTOT + n0 + nb;
        wh = *(const uint4*)(whi + g);
        wl = *(const uint4*)(wlo + g);
    };

    int wm = wid >> 2, wn = wid & 3;
    wmma::fragment<wmma::accumulator, 16, 16, 16, float> acc[2][2];
#pragma unroll
    for (int i = 0; i < 2; i++)
#pragma unroll
        for (int j = 0; j < 2; j++) wmma::fill_fragment(acc[i][j], 0.f);

    uint2 va, nva = make_uint2(0,0);
    uint4 wh, wl, nwh = make_uint4(0,0,0,0), nwl = nwh;
    lda_r(0, va); ldb_r(0, wh, wl);
    for (int c = 0; c < NC; c++) {
        __syncthreads();
        *(uint2*)(As + r * LDA + h) = va;
        *(uint4*)(BsH + kb * LDB + nb) = wh;
        *(uint4*)(BsL + kb * LDB + nb) = wl;
        if (c + 1 < NC) { lda_r(c + 1, nva); ldb_r(c + 1, nwh, nwl); }
        __syncthreads();
        wmma::fragment<wmma::matrix_b, 16, 16, 16, __half, wmma::row_major> fbh[2], fbl[2];
#pragma unroll
        for (int j = 0; j < 2; j++) {
            wmma::load_matrix_sync(fbh[j], BsH + wn * 32 + j * 16, LDB);
            wmma::load_matrix_sync(fbl[j], BsL + wn * 32 + j * 16, LDB);
        }
#pragma unroll
        for (int i = 0; i < 2; i++) {
            wmma::fragment<wmma::matrix_a, 16, 16, 16, __half, wmma::row_major> fa;
            wmma::load_matrix_sync(fa, As + ((wm * 2 + i) * 16) * LDA, LDA);
#pragma unroll
            for (int j = 0; j < 2; j++) {
                wmma::mma_sync(acc[i][j], fa, fbh[j], acc[i][j]);
                wmma::mma_sync(acc[i][j], fa, fbl[j], acc[i][j]);
            }
        }
        va = nva; wh = nwh; wl = nwl;
    }
    __syncthreads();
#pragma unroll
    for (int i = 0; i < 2; i++)
#pragma unroll
        for (int j = 0; j < 2; j++)
            wmma::store_matrix_sync(Cs + ((wm * 2 + i) * 16) * LDC + wn * 32 + j * 16,
                                    acc[i][j], LDC, wmma::mem_row_major);
    __syncthreads();
    {
        int r2 = tid >> 2, ch0 = (tid & 3) * 32;
        long base = (long)(m0 + r2) * NTOT + n0 + ch0;
#pragma unroll
        for (int c = 0; c < 32; c += 4) {
            float4 v;
            v.x = Cs[r2 * LDC + ch0 + c]     + bias[n0 + ch0 + c];
            v.y = Cs[r2 * LDC + ch0 + c + 1] + bias[n0 + ch0 + c + 1];
            v.z = Cs[r2 * LDC + ch0 + c + 2] + bias[n0 + ch0 + c + 2];
            v.w = Cs[r2 * LDC + ch0 + c + 3] + bias[n0 + ch0 + c + 3];
            if (RELU) {
                v.x = fmaxf(v.x, 0.f); v.y = fmaxf(v.y, 0.f);
                v.z = fmaxf(v.z, 0.f); v.w = fmaxf(v.w, 0.f);
            }
            *(float4*)(out + base + c) = v;
        }
    }
}

// ---- LSTM recurrent step (fp32), emits hs as fp16 ----
__global__ void lstm_step(const float* __restrict__ xg, const float* __restrict__ wthh,
                          const float* __restrict__ done, const float* __restrict__ h_in,
                          float* __restrict__ h_out, float* __restrict__ c,
                          __half* __restrict__ hs, int t) {
    constexpr int PAD = 520;
    __shared__ __align__(16) float sh_h[16 * PAD];
    __shared__ __align__(16) float Bs[16][32];
    int tid = threadIdx.x;
    int n0 = blockIdx.x * 32;
#pragma unroll
    for (int i = 0; i < 16; i++) {
        int idx4 = i * 128 + tid;
        int b = idx4 >> 7;
        int qq = idx4 & 127;
        float keep = 1.f - done[t * 16 + b];
        float4 v = ((const float4*)h_in)[idx4];
        v.x *= keep; v.y *= keep; v.z *= keep; v.w *= keep;
        ((float4*)sh_h)[b * (PAD / 4) + qq] = v;
    }
    __syncthreads();
    int tx = tid & 7, ty = tid >> 3;
    float acc[4] = {0.f, 0.f, 0.f, 0.f};
    for (int k0 = 0; k0 < 512; k0 += 16) {
        {
            int kl = tid >> 3, nl = (tid & 7) * 4;
            *(float4*)&Bs[kl][nl] = *(const float4*)&wthh[(k0 + kl) * 2048 + n0 + nl];
        }
        __syncthreads();
#pragma unroll
        for (int kk = 0; kk < 16; kk++) {
            float a = sh_h[ty * PAD + k0 + kk];
            float4 b4 = *(const float4*)&Bs[kk][tx * 4];
            acc[0] += a * b4.x; acc[1] += a * b4.y;
            acc[2] += a * b4.z; acc[3] += a * b4.w;
        }
        __syncthreads();
    }
    int b = ty;
    int u = (n0 >> 2) + tx;
    float4 xv = *(const float4*)&xg[(t * 16 + b) * 2048 + n0 + tx * 4];
    float ig = acc[0] + xv.x, fg = acc[1] + xv.y, gg = acc[2] + xv.z, og = acc[3] + xv.w;
    float keep = 1.f - done[t * 16 + b];
    float cold = c[b * 512 + u] * keep;
    float si = 1.f / (1.f + expf(-ig));
    float sf = 1.f / (1.f + expf(-fg));
    float so = 1.f / (1.f + expf(-og));
    float cn = sf * cold + si * tanhf(gg);
    float hn = so * tanhf(cn);
    c[b * 512 + u] = cn;
    h_out[b * 512 + u] = hn;
    hs[(long)(t * 16 + b) * 512 + u] = __float2half_rn(hn);
}

// ---------------------------------------------------------------------------
extern "C" void kernel_launch(void* const* d_in, const int* in_sizes, int n_in,
                              void* d_out, int out_size) {
    (void)in_sizes; (void)n_in; (void)out_size;
    __half* hh = nullptr;
    float* fa = nullptr;
    cudaGetSymbolAddress((void**)&hh, g_hh);
    cudaGetSymbolAddress((void**)&fa, g_f);

    const float* x    = (const float*)d_in[0];
    const float* done = (const float*)d_in[1];
    const float* h0   = (const float*)d_in[2];
    const float* c0   = (const float*)d_in[3];
    const float* w11  = (const float*)d_in[4];
    const float* b11  = (const float*)d_in[5];
    const float* w12  = (const float*)d_in[6];
    const float* b12  = (const float*)d_in[7];
    const float* w21  = (const float*)d_in[8];
    const float* b21  = (const float*)d_in[9];
    const float* w22  = (const float*)d_in[10];
    const float* b22  = (const float*)d_in[11];
    const float* w31  = (const float*)d_in[12];
    const float* b31  = (const float*)d_in[13];
    const float* w32  = (const float*)d_in[14];
    const float* b32  = (const float*)d_in[15];
    const float* W_ih = (const float*)d_in[16];
    const float* W_hh = (const float*)d_in[17];
    const float* b_ih = (const float*)d_in[18];
    const float* b_hh = (const float*)d_in[19];
    const float* Wf   = (const float*)d_in[20];
    const float* bf   = (const float*)d_in[21];
    float* out = (float*)d_out;

    cudaFuncSetAttribute(ihw_prep_t, cudaFuncAttributeMaxDynamicSharedMemorySize, 69632);

    // ---- prep ----
    xprep<<<14336, 256>>>(x, hh + O_X);
    convw_prep<<<10, 256>>>(w11, hh + O_W1, 4, 32, 80, 1.f / 255.f);
    convw_prep<<<72, 256>>>(w12, hh + O_W2, 32, 32, 576, 1.f);
    convw_prep<<<144, 256>>>(w21, hh + O_W3, 32, 64, 576, 1.f);
    convw_prep<<<288, 256>>>(w22, hh + O_W4, 64, 64, 1152, 1.f);
    convw_prep<<<576, 256>>>(w31, hh + O_W5, 64, 128, 1152, 1.f);
    convw_prep<<<1152, 256>>>(w32, hh + O_W6, 128, 128, 2304, 1.f);
    ihw_prep_t<<<dim3(16, 16), 256, 69632>>>(W_ih, hh + O_WIHH, hh + O_WIHL);
    wf_prep<<<1024, 256>>>(Wf, hh + O_WFH, hh + O_WFL);
    perm_hh<<<4096, 256>>>(W_hh, fa + F_WTHH);
    bias_sum<<<8, 256>>>(b_ih, b_hh, fa + F_BG);
    cudaMemcpyAsync(fa + F_H0, h0, 8192 * sizeof(float), cudaMemcpyDeviceToDevice, 0);
    cudaMemcpyAsync(fa + F_C,  c0, 8192 * sizeof(float), cudaMemcpyDeviceToDevice, 0);

    // ---- conv stack (single-term fp16) ----
    conv_wm4<4, 32, 7, 32, 32, 1><<<24576, 256>>>(hh + O_X, hh + O_W1, b11, hh + O_A1);
    conv_wm4<32, 32, 6, 32, 32, 2><<<5120, 256>>>(hh + O_A1, hh + O_W2, b12, hh + O_A2);
    conv_wm4<32, 64, 5, 16, 16, 1><<<4096, 256>>>(hh + O_A2, hh + O_W3, b21, hh + O_A3);
    conv_wm4<64, 64, 4, 16, 16, 2><<<768, 256>>>(hh + O_A3, hh + O_W4, b22, hh + O_A4);
    conv_wm4<64, 128, 3, 8, 8, 1><<<1024, 256>>>(hh + O_A4, hh + O_W5, b31, hh + O_A5);
    conv_wm4<128, 128, 2, 8, 8, 2><<<128, 256>>>(hh + O_A5, hh + O_W6, b32, hh + O_F);

    // ---- LSTM input GEMM (512 x 2048 x 2048, 2-term weights) ----
    mm_wm3<2048, 2048, false><<<dim3(8, 16), 256>>>(
        hh + O_F, hh + O_WIHH, hh + O_WIHL, fa + F_BG, fa + F_XG);

    // ---- 32 recurrent steps ----
    for (int t = 0; t < 32; t++) {
        float* hin  = fa + ((t & 1) ? F_H1 : F_H0);
        float* hout = fa + ((t & 1) ? F_H0 : F_H1);
        lstm_step<<<64, 128>>>(fa + F_XG, fa + F_WTHH, done, hin, hout,
                               fa + F_C, hh + O_HS, t);
    }

    // ---- final FC + relu into d_out ----
    mm_wm3<512, 512, true><<<dim3(8, 4), 256>>>(
        hh + O_HS, hh + O_WFH, hh + O_WFL, bf, out);

    // ---- hT, cT ----
    cudaMemcpyAsync(out + 262144, fa + F_H0, 8192 * sizeof(float),
                    cudaMemcpyDeviceToDevice, 0);
    cudaMemcpyAsync(out + 270336, fa + F_C, 8192 * sizeof(float),
                    cudaMemcpyDeviceToDevice, 0);
}

// round 9
// speedup vs baseline: 2.2238x; 1.1415x over previous
#include <cuda_runtime.h>
#include <cuda_fp16.h>
#include <mma.h>
#include <stdint.h>

using namespace nvcuda;

// ============================================================================
// CNN(6x conv3d) + LSTM(32) + FC.
// Conv: wmma fp16 single-term.  IH/FC: fp16 2-term (weights 21-bit).
// Double-buffered smem mainloops, one __syncthreads per k-chunk.
// Activations NDHWC fp16.  Weights k-major.
// ============================================================================

__device__ __forceinline__ void splitw(float v, __half& h, __half& l) {
    h = __float2half_rn(v);
    l = __float2half_rn(v - __half2float(h));
}

// ---- fp16 arena ----
#define O_A1  0LL
#define O_A2  100663296LL
#define O_A3  121634816LL
#define O_A4  155189248LL
#define O_A5  161480704LL
#define O_F   169869312LL
#define O_W1  170917888LL
#define O_W2  170923008LL
#define O_W3  170959872LL
#define O_W4  171033600LL
#define O_W5  171181056LL
#define O_W6  171475968LL
#define O_WIHH 172065792LL
#define O_WIHL 176260096LL
#define O_WFH 180454400LL
#define O_WFL 180716544LL
#define O_X   180978688LL
#define O_HS  195658752LL
#define H_TOTAL 195920896LL
__device__ __half g_hh[H_TOTAL];

// ---- fp32 arena ----
#define F_XG   0LL
#define F_WTHH 1048576LL
#define F_BG   2097152LL
#define F_H0   2099200LL
#define F_H1   2107392LL
#define F_C    2115584LL
#define F_TOTAL 2123776LL
__device__ float g_f[F_TOTAL];

// ---- prep kernels ----
__global__ void xprep(const float* __restrict__ x, __half* __restrict__ xo) {
    long i = ((long)blockIdx.x * blockDim.x + threadIdx.x) * 4;
    float4 v = *(const float4*)(x + i);
    __half2 a = __floats2half2_rn(v.x, v.y);
    __half2 b = __floats2half2_rn(v.z, v.w);
    uint2 p;
    p.x = *reinterpret_cast<uint32_t*>(&a);
    p.y = *reinterpret_cast<uint32_t*>(&b);
    *(uint2*)(xo + i) = p;
}
__global__ void convw_prep(const float* __restrict__ src, __half* __restrict__ dw,
                           int CIN, int COUT, int Kpad, float scale) {
    int i = blockIdx.x * blockDim.x + threadIdx.x;
    if (i >= COUT * Kpad) return;
    int co = i / Kpad, kk = i % Kpad;
    float v = 0.f;
    if (kk < CIN * 18) {
        int cin = kk % CIN, tap = kk / CIN;
        v = src[(co * CIN + cin) * 18 + tap] * scale;
    }
    dw[(long)kk * COUT + co] = __float2half_rn(v);
}
// W_ih permute: dst[k2*2048 + n2], k2 = sp*128+c (k = c*16+sp), n2 = u*4+g.
__global__ void ihw_prep_t(const float* __restrict__ src,
                           __half* __restrict__ dh, __half* __restrict__ dl) {
    extern __shared__ __half ts[];                  // [2][128][136]
    __half* TH = ts;
    __half* TL = ts + 128 * 136;
    int tid = threadIdx.x;
    int kb = blockIdx.x * 128, nbv = blockIdx.y * 128;
    {
        int n2 = nbv + (tid >> 1);
        int g = n2 & 3, u = n2 >> 2;
        const float* srow = src + (long)(g * 512 + u) * 2048 + kb + (tid & 1) * 64;
        int klo = (tid & 1) * 64, col = tid >> 1;
#pragma unroll
        for (int q = 0; q < 16; q++) {
            float4 v = *(const float4*)(srow + q * 4);
            float vv[4] = {v.x, v.y, v.z, v.w};
#pragma unroll
            for (int e = 0; e < 4; e++) {
                __half h, l;
                splitw(vv[e], h, l);
                TH[(klo + q * 4 + e) * 136 + col] = h;
                TL[(klo + q * 4 + e) * 136 + col] = l;
            }
        }
    }
    __syncthreads();
    {
        int kl = tid >> 1, nh = (tid & 1) * 64;
        int cl = kl >> 4, sp = kl & 15;
        int k2 = sp * 128 + (kb >> 4) + cl;
        long base = (long)k2 * 2048 + nbv + nh;
#pragma unroll
        for (int q = 0; q < 8; q++) {
            *(uint4*)(dh + base + q * 8) = *(const uint4*)(TH + kl * 136 + nh + q * 8);
            *(uint4*)(dl + base + q * 8) = *(const uint4*)(TL + kl * 136 + nh + q * 8);
        }
    }
}
__global__ void wf_prep(const float* __restrict__ src, __half* __restrict__ dh,
                        __half* __restrict__ dl) {
    int i = blockIdx.x * blockDim.x + threadIdx.x;
    if (i >= 512 * 512) return;
    int n = i >> 9, k = i & 511;
    __half h, l;
    splitw(src[i], h, l);
    long o = (long)k * 512 + n;
    dh[o] = h;
    dl[o] = l;
}
__global__ void perm_hh(const float* __restrict__ src, float* __restrict__ dst) {
    int i = blockIdx.x * blockDim.x + threadIdx.x;
    if (i < 2048 * 512) {
        int r = i >> 9, k = i & 511;
        int g = r >> 9, u = r & 511;
        dst[k * 2048 + (u << 2) + g] = src[i];
    }
}
__global__ void bias_sum(const float* __restrict__ bi, const float* __restrict__ bh2,
                         float* __restrict__ dst) {
    int i = blockIdx.x * blockDim.x + threadIdx.x;
    if (i < 2048) {
        int g = i >> 9, u = i & 511;
        dst[(u << 2) + g] = bi[i] + bh2[i];
    }
}

// ============================================================================
// wmma implicit-GEMM conv, fp16 single-term, double-buffered smem.
// CTA: BM x COUT, BK=16, one sync per chunk.
// ============================================================================
template <int CIN, int COUT, int DIN, int HIN, int WIN, int S>
__global__ __launch_bounds__(256) void conv_wm5(
    const __half* __restrict__ ain, const __half* __restrict__ wgt,
    const float* __restrict__ bias, __half* __restrict__ aout) {
    constexpr int DOUT = DIN - 1;
    constexpr int HOUT = (S == 1) ? HIN : HIN / 2;
    constexpr int WOUT = (S == 1) ? WIN : WIN / 2;
    constexpr int Kpad = (CIN == 4) ? 80 : CIN * 18;
    constexpr int NC = Kpad / 16;
    constexpr int BM = (COUT >= 128) ? 64 : 128;
    constexpr int TPR = 256 / BM;
    constexpr int HS = 16 / TPR;
    constexpr int WN = (COUT >= 128) ? 4 : (COUT / 32);
    constexpr int WM = 8 / WN, MF = BM / (WM * 16);
    constexpr int LDA = 24, LDB = COUT + 8, LDC = COUT + 4;
    constexpr int ASZ = BM * LDA, BSZ = 16 * LDB;
    constexpr int SST = ASZ + BSZ;
    constexpr int L2C = (CIN == 32) ? 5 : ((CIN == 64) ? 6 : 7);
    constexpr int LOADSZ = 2 * SST * 2;
    constexpr int CSZ = BM * LDC * 4;
    constexpr int SMSZ = (LOADSZ > CSZ) ? LOADSZ : CSZ;

    __shared__ __align__(16) char sm[SMSZ];
    __half* smb = (__half*)sm;
    float* Cs = (float*)sm;

    int tid = threadIdx.x, wid = tid >> 5;
    int m0 = blockIdx.x * BM;
    int r = tid / TPR;
    int h = (tid % TPR) * HS;
    int m = m0 + r;
    int ow = m % WOUT; int t1 = m / WOUT;
    int oh = t1 % HOUT; int t2 = t1 / HOUT;
    int od = t2 % DOUT; int bb = t2 / DOUT;

    constexpr int TPK = COUT / 8;
    int kb = tid / TPK, nb = (tid % TPK) * 8;
    bool bact = kb < 16;

    auto lda_r = [&](int c, uint4& va) {
        va = make_uint4(0u, 0u, 0u, 0u);
        if constexpr (CIN == 4) {
            int kk = c * 16 + h;
#pragma unroll
            for (int t = 0; t < 2; t++) {
                int tap = kk / 4 + t;
                if (tap < 18) {
                    int kd = (tap >= 9) ? 1 : 0; int rr = tap - 9 * kd;
                    int kh = rr / 3, kw = rr - 3 * kh;
                    int ih = oh - 1 + kh, iw = ow - 1 + kw;
                    if ((unsigned)ih < (unsigned)HIN && (unsigned)iw < (unsigned)WIN) {
                        long g = ((((long)bb * DIN + od + kd) * HIN + ih) * WIN + iw) * 4;
                        uint2 xh = *(const uint2*)(ain + g);
                        if (t == 0) { va.x = xh.x; va.y = xh.y; }
                        else        { va.z = xh.x; va.w = xh.y; }
                    }
                }
            }
        } else {
            int kk = c * 16 + h;
            int tap = kk >> L2C, cin = kk & (CIN - 1);
            int kd = (tap >= 9) ? 1 : 0; int rr = tap - 9 * kd;
            int kh = rr / 3, kw = rr - 3 * kh;
            int ih = oh * S - 1 + kh, iw = ow * S - 1 + kw;
            if ((unsigned)ih < (unsigned)HIN && (unsigned)iw < (unsigned)WIN) {
                long g = ((((long)bb * DIN + od + kd) * HIN + ih) * WIN + iw) * CIN + cin;
                if constexpr (TPR == 2) {
                    va = *(const uint4*)(ain + g);
                } else {
                    uint2 xh = *(const uint2*)(ain + g);
                    va.x = xh.x; va.y = xh.y;
                }
            }
        }
    };
    auto ldb_r = [&](int c, uint4& wv) {
        if (bact) {
            wv = *(const uint4*)(wgt + (long)(c * 16 + kb) * COUT + nb);
        }
    };
    auto store_st = [&](int st, const uint4& va, const uint4& wv) {
        __half* As = smb + st * SST;
        __half* Bs = As + ASZ;
        if constexpr (TPR == 2) {
            *(uint4*)(As + r * LDA + h) = va;
        } else {
            *(uint2*)(As + r * LDA + h) = make_uint2(va.x, va.y);
        }
        if (bact) {
            *(uint4*)(Bs + kb * LDB + nb) = wv;
        }
    };

    int wm = wid / WN, wn = wid % WN;
    wmma::fragment<wmma::accumulator, 16, 16, 16, float> acc[MF][2];
#pragma unroll
    for (int i = 0; i < MF; i++)
#pragma unroll
        for (int j = 0; j < 2; j++) wmma::fill_fragment(acc[i][j], 0.f);

    uint4 va = make_uint4(0,0,0,0), wv = va, nva = va, nwv = va;
    lda_r(0, va); ldb_r(0, wv);
    store_st(0, va, wv);
    __syncthreads();
    for (int c = 0; c < NC; c++) {
        int st = c & 1;
        if (c + 1 < NC) { lda_r(c + 1, nva); ldb_r(c + 1, nwv); }
        const __half* As = smb + st * SST;
        const __half* Bs = As + ASZ;
        wmma::fragment<wmma::matrix_b, 16, 16, 16, __half, wmma::row_major> fb[2];
#pragma unroll
        for (int j = 0; j < 2; j++)
            wmma::load_matrix_sync(fb[j], Bs + wn * 32 + j * 16, LDB);
#pragma unroll
        for (int i = 0; i < MF; i++) {
            wmma::fragment<wmma::matrix_a, 16, 16, 16, __half, wmma::row_major> fa;
            wmma::load_matrix_sync(fa, As + ((wm * MF + i) * 16) * LDA, LDA);
#pragma unroll
            for (int j = 0; j < 2; j++)
                wmma::mma_sync(acc[i][j], fa, fb[j], acc[i][j]);
        }
        if (c + 1 < NC) {
            store_st(st ^ 1, nva, nwv);
            __syncthreads();
        }
    }
    __syncthreads();
#pragma unroll
    for (int i = 0; i < MF; i++)
#pragma unroll
        for (int j = 0; j < 2; j++)
            wmma::store_matrix_sync(Cs + ((wm * MF + i) * 16) * LDC + wn * 32 + j * 16,
                                    acc[i][j], LDC, wmma::mem_row_major);
    __syncthreads();
    {
        int r2 = tid / TPR, ch0 = (tid % TPR) * (COUT / TPR);
        long base = (long)(m0 + r2) * COUT + ch0;
#pragma unroll
        for (int c = 0; c < COUT / TPR; c += 4) {
            float v0 = fmaxf(Cs[r2 * LDC + ch0 + c]     + bias[ch0 + c], 0.f);
            float v1 = fmaxf(Cs[r2 * LDC + ch0 + c + 1] + bias[ch0 + c + 1], 0.f);
            float v2 = fmaxf(Cs[r2 * LDC + ch0 + c + 2] + bias[ch0 + c + 2], 0.f);
            float v3 = fmaxf(Cs[r2 * LDC + ch0 + c + 3] + bias[ch0 + c + 3], 0.f);
            __half2 p0 = __floats2half2_rn(v0, v1);
            __half2 p1 = __floats2half2_rn(v2, v3);
            uint2 p;
            p.x = *reinterpret_cast<uint32_t*>(&p0);
            p.y = *reinterpret_cast<uint32_t*>(&p1);
            *(uint2*)(aout + base + c) = p;
        }
    }
}

// ============================================================================
// wmma GEMM fp16 2-term, fp32 out, double-buffered.  CTA: 64 x 128, BK=16.
// ============================================================================
template <int NTOT, int K, bool RELU>
__global__ __launch_bounds__(256) void mm_wm4(
    const __half* __restrict__ ain,
    const __half* __restrict__ whi, const __half* __restrict__ wlo,
    const float* __restrict__ bias, float* __restrict__ out) {
    constexpr int NC = K / 16;
    constexpr int LDA = 24, LDB = 136, LDC = 132;
    constexpr int ASZ = 64 * LDA, BSZ = 16 * LDB;
    constexpr int SST = ASZ + 2 * BSZ;
    constexpr int LOADSZ = 2 * SST * 2;
    constexpr int CSZ = 64 * LDC * 4;
    constexpr int SMSZ = (LOADSZ > CSZ) ? LOADSZ : CSZ;

    __shared__ __align__(16) char sm[SMSZ];
    __half* smb = (__half*)sm;
    float* Cs = (float*)sm;

    int tid = threadIdx.x, wid = tid >> 5;
    int m0 = blockIdx.x * 64, n0 = blockIdx.y * 128;
    int r = tid >> 2, h = (tid & 3) * 4;
    long mrow = m0 + r;
    int kb = tid >> 4, nb = (tid & 15) * 8;

    auto lda_r = [&](int c, uint2& va) {
        va = *(const uint2*)(ain + mrow * K + c * 16 + h);
    };
    auto ldb_r = [&](int c, uint4& wh, uint4& wl) {
        long g = (long)(c * 16 + kb) * NTOT + n0 + nb;
        wh = *(const uint4*)(whi + g);
        wl = *(const uint4*)(wlo + g);
    };
    auto store_st = [&](int st, const uint2& va, const uint4& wh, const uint4& wl) {
        __half* As = smb + st * SST;
        __half* BsH = As + ASZ;
        __half* BsL = BsH + BSZ;
        *(uint2*)(As + r * LDA + h) = va;
        *(uint4*)(BsH + kb * LDB + nb) = wh;
        *(uint4*)(BsL + kb * LDB + nb) = wl;
    };

    int wm = wid >> 2, wn = wid & 3;
    wmma::fragment<wmma::accumulator, 16, 16, 16, float> acc[2][2];
#pragma unroll
    for (int i = 0; i < 2; i++)
#pragma unroll
        for (int j = 0; j < 2; j++) wmma::fill_fragment(acc[i][j], 0.f);

    uint2 va, nva = make_uint2(0,0);
    uint4 wh, wl, nwh = make_uint4(0,0,0,0), nwl = nwh;
    lda_r(0, va); ldb_r(0, wh, wl);
    store_st(0, va, wh, wl);
    __syncthreads();
    for (int c = 0; c < NC; c++) {
        int st = c & 1;
        if (c + 1 < NC) { lda_r(c + 1, nva); ldb_r(c + 1, nwh, nwl); }
        const __half* As = smb + st * SST;
        const __half* BsH = As + ASZ;
        const __half* BsL = BsH + BSZ;
        wmma::fragment<wmma::matrix_b, 16, 16, 16, __half, wmma::row_major> fbh[2], fbl[2];
#pragma unroll
        for (int j = 0; j < 2; j++) {
            wmma::load_matrix_sync(fbh[j], BsH + wn * 32 + j * 16, LDB);
            wmma::load_matrix_sync(fbl[j], BsL + wn * 32 + j * 16, LDB);
        }
#pragma unroll
        for (int i = 0; i < 2; i++) {
            wmma::fragment<wmma::matrix_a, 16, 16, 16, __half, wmma::row_major> fa;
            wmma::load_matrix_sync(fa, As + ((wm * 2 + i) * 16) * LDA, LDA);
#pragma unroll
            for (int j = 0; j < 2; j++) {
                wmma::mma_sync(acc[i][j], fa, fbh[j], acc[i][j]);
                wmma::mma_sync(acc[i][j], fa, fbl[j], acc[i][j]);
            }
        }
        if (c + 1 < NC) {
            store_st(st ^ 1, nva, nwh, nwl);
            __syncthreads();
        }
    }
    __syncthreads();
#pragma unroll
    for (int i = 0; i < 2; i++)
#pragma unroll
        for (int j = 0; j < 2; j++)
            wmma::store_matrix_sync(Cs + ((wm * 2 + i) * 16) * LDC + wn * 32 + j * 16,
                                    acc[i][j], LDC, wmma::mem_row_major);
    __syncthreads();
    {
        int r2 = tid >> 2, ch0 = (tid & 3) * 32;
        long base = (long)(m0 + r2) * NTOT + n0 + ch0;
#pragma unroll
        for (int c = 0; c < 32; c += 4) {
            float4 v;
            v.x = Cs[r2 * LDC + ch0 + c]     + bias[n0 + ch0 + c];
            v.y = Cs[r2 * LDC + ch0 + c + 1] + bias[n0 + ch0 + c + 1];
            v.z = Cs[r2 * LDC + ch0 + c + 2] + bias[n0 + ch0 + c + 2];
            v.w = Cs[r2 * LDC + ch0 + c + 3] + bias[n0 + ch0 + c + 3];
            if (RELU) {
                v.x = fmaxf(v.x, 0.f); v.y = fmaxf(v.y, 0.f);
                v.z = fmaxf(v.z, 0.f); v.w = fmaxf(v.w, 0.f);
            }
            *(float4*)(out + base + c) = v;
        }
    }
}

// ---- LSTM recurrent step: BK=32, double-buffered W tile, reg prefetch ----
__global__ void lstm_step(const float* __restrict__ xg, const float* __restrict__ wthh,
                          const float* __restrict__ done, const float* __restrict__ h_in,
                          float* __restrict__ h_out, float* __restrict__ c,
                          __half* __restrict__ hs, int t) {
    constexpr int PAD = 520;
    __shared__ __align__(16) float sh_h[16 * PAD];
    __shared__ __align__(16) float Bs[2][32][36];
    int tid = threadIdx.x;
    int n0 = blockIdx.x * 32;
#pragma unroll
    for (int i = 0; i < 16; i++) {
        int idx4 = i * 128 + tid;
        int b = idx4 >> 7;
        int qq = idx4 & 127;
        float keep = 1.f - done[t * 16 + b];
        float4 v = ((const float4*)h_in)[idx4];
        v.x *= keep; v.y *= keep; v.z *= keep; v.w *= keep;
        ((float4*)sh_h)[b * (PAD / 4) + qq] = v;
    }
    // W loader mapping: 256 float4 per 32x32 chunk, 2 per thread
    int f0 = tid * 2;
    int row0 = f0 >> 3, col0 = (f0 & 7) * 4;
    int row1 = (f0 + 1) >> 3, col1 = ((f0 + 1) & 7) * 4;

    auto ldw = [&](int k0, float4& w0, float4& w1) {
        w0 = *(const float4*)&wthh[(k0 + row0) * 2048 + n0 + col0];
        w1 = *(const float4*)&wthh[(k0 + row1) * 2048 + n0 + col1];
    };
    float4 w0, w1, nw0, nw1;
    ldw(0, w0, w1);
    *(float4*)&Bs[0][row0][col0] = w0;
    *(float4*)&Bs[0][row1][col1] = w1;
    __syncthreads();

    int tx = tid & 7, ty = tid >> 3;
    float acc[4] = {0.f, 0.f, 0.f, 0.f};
    for (int cch = 0; cch < 16; cch++) {
        int st = cch & 1;
        if (cch + 1 < 16) ldw((cch + 1) * 32, nw0, nw1);
        int k0 = cch * 32;
#pragma unroll
        for (int kk = 0; kk < 32; kk++) {
            float a = sh_h[ty * PAD + k0 + kk];
            float4 b4 = *(const float4*)&Bs[st][kk][tx * 4];
            acc[0] += a * b4.x; acc[1] += a * b4.y;
            acc[2] += a * b4.z; acc[3] += a * b4.w;
        }
        if (cch + 1 < 16) {
            *(float4*)&Bs[st ^ 1][row0][col0] = nw0;
            *(float4*)&Bs[st ^ 1][row1][col1] = nw1;
            __syncthreads();
        }
    }
    int b = ty;
    int u = (n0 >> 2) + tx;
    float4 xv = *(const float4*)&xg[(t * 16 + b) * 2048 + n0 + tx * 4];
    float ig = acc[0] + xv.x, fg = acc[1] + xv.y, gg = acc[2] + xv.z, og = acc[3] + xv.w;
    float keep = 1.f - done[t * 16 + b];
    float cold = c[b * 512 + u] * keep;
    float si = 1.f / (1.f + expf(-ig));
    float sf = 1.f / (1.f + expf(-fg));
    float so = 1.f / (1.f + expf(-og));
    float cn = sf * cold + si * tanhf(gg);
    float hn = so * tanhf(cn);
    c[b * 512 + u] = cn;
    h_out[b * 512 + u] = hn;
    hs[(long)(t * 16 + b) * 512 + u] = __float2half_rn(hn);
}

// ---------------------------------------------------------------------------
extern "C" void kernel_launch(void* const* d_in, const int* in_sizes, int n_in,
                              void* d_out, int out_size) {
    (void)in_sizes; (void)n_in; (void)out_size;
    __half* hh = nullptr;
    float* fa = nullptr;
    cudaGetSymbolAddress((void**)&hh, g_hh);
    cudaGetSymbolAddress((void**)&fa, g_f);

    const float* x    = (const float*)d_in[0];
    const float* done = (const float*)d_in[1];
    const float* h0   = (const float*)d_in[2];
    const float* c0   = (const float*)d_in[3];
    const float* w11  = (const float*)d_in[4];
    const float* b11  = (const float*)d_in[5];
    const float* w12  = (const float*)d_in[6];
    const float* b12  = (const float*)d_in[7];
    const float* w21  = (const float*)d_in[8];
    const float* b21  = (const float*)d_in[9];
    const float* w22  = (const float*)d_in[10];
    const float* b22  = (const float*)d_in[11];
    const float* w31  = (const float*)d_in[12];
    const float* b31  = (const float*)d_in[13];
    const float* w32  = (const float*)d_in[14];
    const float* b32  = (const float*)d_in[15];
    const float* W_ih = (const float*)d_in[16];
    const float* W_hh = (const float*)d_in[17];
    const float* b_ih = (const float*)d_in[18];
    const float* b_hh = (const float*)d_in[19];
    const float* Wf   = (const float*)d_in[20];
    const float* bf   = (const float*)d_in[21];
    float* out = (float*)d_out;

    cudaFuncSetAttribute(ihw_prep_t, cudaFuncAttributeMaxDynamicSharedMemorySize, 69632);

    // ---- prep ----
    xprep<<<14336, 256>>>(x, hh + O_X);
    convw_prep<<<10, 256>>>(w11, hh + O_W1, 4, 32, 80, 1.f / 255.f);
    convw_prep<<<72, 256>>>(w12, hh + O_W2, 32, 32, 576, 1.f);
    convw_prep<<<144, 256>>>(w21, hh + O_W3, 32, 64, 576, 1.f);
    convw_prep<<<288, 256>>>(w22, hh + O_W4, 64, 64, 1152, 1.f);
    convw_prep<<<576, 256>>>(w31, hh + O_W5, 64, 128, 1152, 1.f);
    convw_prep<<<1152, 256>>>(w32, hh + O_W6, 128, 128, 2304, 1.f);
    ihw_prep_t<<<dim3(16, 16), 256, 69632>>>(W_ih, hh + O_WIHH, hh + O_WIHL);
    wf_prep<<<1024, 256>>>(Wf, hh + O_WFH, hh + O_WFL);
    perm_hh<<<4096, 256>>>(W_hh, fa + F_WTHH);
    bias_sum<<<8, 256>>>(b_ih, b_hh, fa + F_BG);
    cudaMemcpyAsync(fa + F_H0, h0, 8192 * sizeof(float), cudaMemcpyDeviceToDevice, 0);
    cudaMemcpyAsync(fa + F_C,  c0, 8192 * sizeof(float), cudaMemcpyDeviceToDevice, 0);

    // ---- conv stack (single-term fp16, double-buffered) ----
    conv_wm5<4, 32, 7, 32, 32, 1><<<24576, 256>>>(hh + O_X, hh + O_W1, b11, hh + O_A1);
    conv_wm5<32, 32, 6, 32, 32, 2><<<5120, 256>>>(hh + O_A1, hh + O_W2, b12, hh + O_A2);
    conv_wm5<32, 64, 5, 16, 16, 1><<<4096, 256>>>(hh + O_A2, hh + O_W3, b21, hh + O_A3);
    conv_wm5<64, 64, 4, 16, 16, 2><<<768, 256>>>(hh + O_A3, hh + O_W4, b22, hh + O_A4);
    conv_wm5<64, 128, 3, 8, 8, 1><<<1024, 256>>>(hh + O_A4, hh + O_W5, b31, hh + O_A5);
    conv_wm5<128, 128, 2, 8, 8, 2><<<128, 256>>>(hh + O_A5, hh + O_W6, b32, hh + O_F);

    // ---- LSTM input GEMM (512 x 2048 x 2048, 2-term weights) ----
    mm_wm4<2048, 2048, false><<<dim3(8, 16), 256>>>(
        hh + O_F, hh + O_WIHH, hh + O_WIHL, fa + F_BG, fa + F_XG);

    // ---- 32 recurrent steps ----
    for (int t = 0; t < 32; t++) {
        float* hin  = fa + ((t & 1) ? F_H1 : F_H0);
        float* hout = fa + ((t & 1) ? F_H0 : F_H1);
        lstm_step<<<64, 128>>>(fa + F_XG, fa + F_WTHH, done, hin, hout,
                               fa + F_C, hh + O_HS, t);
    }

    // ---- final FC + relu into d_out ----
    mm_wm4<512, 512, true><<<dim3(8, 4), 256>>>(
        hh + O_HS, hh + O_WFH, hh + O_WFL, bf, out);

    // ---- hT, cT ----
    cudaMemcpyAsync(out + 262144, fa + F_H0, 8192 * sizeof(float),
                    cudaMemcpyDeviceToDevice, 0);
    cudaMemcpyAsync(out + 270336, fa + F_C, 8192 * sizeof(float),
                    cudaMemcpyDeviceToDevice, 0);
}

// round 10
// speedup vs baseline: 2.5100x; 1.1287x over previous
#include <cuda_runtime.h>
#include <cuda_fp16.h>
#include <mma.h>
#include <stdint.h>

using namespace nvcuda;

// ============================================================================
// CNN(6x conv3d) + LSTM(32) + FC.
// Conv: wmma fp16 single-term, BK=32 double-buffered.  IH/FC: fp16 2-term.
// LSTM: persistent kernel, W_hh resident in smem, grid barrier between steps.
// Activations NDHWC fp16.  Weights k-major.
// ============================================================================

__device__ __forceinline__ void splitw(float v, __half& h, __half& l) {
    h = __float2half_rn(v);
    l = __float2half_rn(v - __half2float(h));
}

// ---- fp16 arena ----
#define O_A1  0LL
#define O_A2  100663296LL
#define O_A3  121634816LL
#define O_A4  155189248LL
#define O_A5  161480704LL
#define O_F   169869312LL
#define O_W1  170917888LL
#define O_W2  170923008LL
#define O_W3  170959872LL
#define O_W4  171033600LL
#define O_W5  171181056LL
#define O_W6  171475968LL
#define O_WIHH 172065792LL
#define O_WIHL 176260096LL
#define O_WFH 180454400LL
#define O_WFL 180716544LL
#define O_X   180978688LL
#define O_HS  195658752LL
#define H_TOTAL 195920896LL
__device__ __half g_hh[H_TOTAL];

// ---- fp32 arena ----
#define F_XG   0LL
#define F_WTHH 1048576LL
#define F_BG   2097152LL
#define F_H0   2099200LL
#define F_H1   2107392LL
#define F_C    2115584LL
#define F_BAR  2123776LL
#define F_TOTAL 2123780LL
__device__ float g_f[F_TOTAL];

// ---- prep kernels ----
__global__ void xprep(const float* __restrict__ x, __half* __restrict__ xo) {
    long i = ((long)blockIdx.x * blockDim.x + threadIdx.x) * 4;
    float4 v = *(const float4*)(x + i);
    __half2 a = __floats2half2_rn(v.x, v.y);
    __half2 b = __floats2half2_rn(v.z, v.w);
    uint2 p;
    p.x = *reinterpret_cast<uint32_t*>(&a);
    p.y = *reinterpret_cast<uint32_t*>(&b);
    *(uint2*)(xo + i) = p;
}
// All 6 conv weight preps in one launch.  Layer l: (COUT,CIN,2,3,3) fp32 ->
// k-major fp16 [kk*COUT+co], kk = tap*CIN+cin, K padded.
__global__ void convw_all(const float* s1, const float* s2, const float* s3,
                          const float* s4, const float* s5, const float* s6,
                          __half* d1, __half* d2, __half* d3,
                          __half* d4, __half* d5, __half* d6) {
    int i = blockIdx.x * blockDim.x + threadIdx.x;
    const float* src; __half* dst;
    int CIN, COUT, Kpad; float scale = 1.f;
    if (i < 3072)        { src = s1; dst = d1; CIN = 4;   COUT = 32;  Kpad = 96;   scale = 1.f / 255.f; }
    else if (i < 21504)  { src = s2; dst = d2; CIN = 32;  COUT = 32;  Kpad = 576;  i -= 3072; }
    else if (i < 58368)  { src = s3; dst = d3; CIN = 32;  COUT = 64;  Kpad = 576;  i -= 21504; }
    else if (i < 132096) { src = s4; dst = d4; CIN = 64;  COUT = 64;  Kpad = 1152; i -= 58368; }
    else if (i < 279552) { src = s5; dst = d5; CIN = 64;  COUT = 128; Kpad = 1152; i -= 132096; }
    else if (i < 574464) { src = s6; dst = d6; CIN = 128; COUT = 128; Kpad = 2304; i -= 279552; }
    else return;
    int co = i / Kpad, kk = i % Kpad;
    float v = 0.f;
    if (kk < CIN * 18) {
        int cin = kk % CIN, tap = kk / CIN;
        v = src[(co * CIN + cin) * 18 + tap] * scale;
    }
    dst[(long)kk * COUT + co] = __float2half_rn(v);
}
// W_ih permute: dst[k2*2048 + n2], k2 = sp*128+c (k = c*16+sp), n2 = u*4+g.
__global__ void ihw_prep_t(const float* __restrict__ src,
                           __half* __restrict__ dh, __half* __restrict__ dl) {
    extern __shared__ __half ts[];                  // [2][128][136]
    __half* TH = ts;
    __half* TL = ts + 128 * 136;
    int tid = threadIdx.x;
    int kb = blockIdx.x * 128, nbv = blockIdx.y * 128;
    {
        int n2 = nbv + (tid >> 1);
        int g = n2 & 3, u = n2 >> 2;
        const float* srow = src + (long)(g * 512 + u) * 2048 + kb + (tid & 1) * 64;
        int klo = (tid & 1) * 64, col = tid >> 1;
#pragma unroll
        for (int q = 0; q < 16; q++) {
            float4 v = *(const float4*)(srow + q * 4);
            float vv[4] = {v.x, v.y, v.z, v.w};
#pragma unroll
            for (int e = 0; e < 4; e++) {
                __half h, l;
                splitw(vv[e], h, l);
                TH[(klo + q * 4 + e) * 136 + col] = h;
                TL[(klo + q * 4 + e) * 136 + col] = l;
            }
        }
    }
    __syncthreads();
    {
        int kl = tid >> 1, nh = (tid & 1) * 64;
        int cl = kl >> 4, sp = kl & 15;
        int k2 = sp * 128 + (kb >> 4) + cl;
        long base = (long)k2 * 2048 + nbv + nh;
#pragma unroll
        for (int q = 0; q < 8; q++) {
            *(uint4*)(dh + base + q * 8) = *(const uint4*)(TH + kl * 136 + nh + q * 8);
            *(uint4*)(dl + base + q * 8) = *(const uint4*)(TL + kl * 136 + nh + q * 8);
        }
    }
}
__global__ void wf_prep(const float* __restrict__ src, __half* __restrict__ dh,
                        __half* __restrict__ dl) {
    int i = blockIdx.x * blockDim.x + threadIdx.x;
    if (i >= 512 * 512) return;
    int n = i >> 9, k = i & 511;
    __half h, l;
    splitw(src[i], h, l);
    long o = (long)k * 512 + n;
    dh[o] = h;
    dl[o] = l;
}
__global__ void perm_hh(const float* __restrict__ src, float* __restrict__ dst) {
    int i = blockIdx.x * blockDim.x + threadIdx.x;
    if (i < 2048 * 512) {
        int r = i >> 9, k = i & 511;
        int g = r >> 9, u = r & 511;
        dst[k * 2048 + (u << 2) + g] = src[i];
    }
}
__global__ void bias_sum(const float* __restrict__ bi, const float* __restrict__ bh2,
                         float* __restrict__ dst) {
    int i = blockIdx.x * blockDim.x + threadIdx.x;
    if (i < 2048) {
        int g = i >> 9, u = i & 511;
        dst[(u << 2) + g] = bi[i] + bh2[i];
    }
}

// ============================================================================
// wmma implicit-GEMM conv, fp16 single-term, BK=32, double-buffered smem.
// ============================================================================
template <int CIN, int COUT, int DIN, int HIN, int WIN, int S>
__global__ __launch_bounds__(256) void conv_wm6(
    const __half* __restrict__ ain, const __half* __restrict__ wgt,
    const float* __restrict__ bias, __half* __restrict__ aout) {
    constexpr int DOUT = DIN - 1;
    constexpr int HOUT = (S == 1) ? HIN : HIN / 2;
    constexpr int WOUT = (S == 1) ? WIN : WIN / 2;
    constexpr int Kpad = (CIN == 4) ? 96 : CIN * 18;
    constexpr int NC = Kpad / 32;
    constexpr int BM = (COUT >= 128) ? 64 : 128;
    constexpr int TPR = 256 / BM;               // 2 or 4 threads per A row
    constexpr int HS = 32 / TPR;                // 16 or 8 k per thread
    constexpr int WN = (COUT >= 128) ? 4 : (COUT / 32);
    constexpr int WM = 8 / WN, MF = BM / (WM * 16);
    constexpr int LDA = 40, LDB = COUT + 8, LDC = COUT + 4;
    constexpr int ASZ = BM * LDA, BSZ = 32 * LDB;
    constexpr int SST = ASZ + BSZ;
    constexpr int L2C = (CIN == 32) ? 5 : ((CIN == 64) ? 6 : 7);
    constexpr int LOADSZ = 2 * SST * 2;
    constexpr int CSZ = BM * LDC * 4;
    constexpr int SMSZ = (LOADSZ > CSZ) ? LOADSZ : CSZ;

    __shared__ __align__(16) char sm[SMSZ];
    __half* smb = (__half*)sm;
    float* Cs = (float*)sm;

    int tid = threadIdx.x, wid = tid >> 5;
    int m0 = blockIdx.x * BM;
    int r = tid / TPR;
    int h = (tid % TPR) * HS;
    int m = m0 + r;
    int ow = m % WOUT; int t1 = m / WOUT;
    int oh = t1 % HOUT; int t2 = t1 / HOUT;
    int od = t2 % DOUT; int bb = t2 / DOUT;

    constexpr int TPK = COUT / 8;
    int kb = tid / TPK, nb = (tid % TPK) * 8;
    bool bact = kb < 32;

    auto lda_r = [&](int c, uint4* va) {
        va[0] = make_uint4(0u, 0u, 0u, 0u);
        va[1] = va[0];
        if constexpr (CIN == 4) {
            int kk0 = c * 32 + h;                // TPR==2, HS==16: 4 taps
            uint2 tv[4];
#pragma unroll
            for (int j = 0; j < 4; j++) {
                tv[j] = make_uint2(0u, 0u);
                int tap = (kk0 >> 2) + j;
                if (tap < 18) {
                    int kd = (tap >= 9) ? 1 : 0; int rr = tap - 9 * kd;
                    int kh = rr / 3, kw = rr - 3 * kh;
                    int ih = oh - 1 + kh, iw = ow - 1 + kw;
                    if ((unsigned)ih < (unsigned)HIN && (unsigned)iw < (unsigned)WIN) {
                        long g = ((((long)bb * DIN + od + kd) * HIN + ih) * WIN + iw) * 4;
                        tv[j] = *(const uint2*)(ain + g);
                    }
                }
            }
            va[0] = make_uint4(tv[0].x, tv[0].y, tv[1].x, tv[1].y);
            va[1] = make_uint4(tv[2].x, tv[2].y, tv[3].x, tv[3].y);
        } else {
            int kk = c * 32 + h;
            int tap = kk >> L2C, cin = kk & (CIN - 1);
            int kd = (tap >= 9) ? 1 : 0; int rr = tap - 9 * kd;
            int kh = rr / 3, kw = rr - 3 * kh;
            int ih = oh * S - 1 + kh, iw = ow * S - 1 + kw;
            if ((unsigned)ih < (unsigned)HIN && (unsigned)iw < (unsigned)WIN) {
                long g = ((((long)bb * DIN + od + kd) * HIN + ih) * WIN + iw) * CIN + cin;
                va[0] = *(const uint4*)(ain + g);
                if constexpr (TPR == 2) va[1] = *(const uint4*)(ain + g + 8);
            }
        }
    };
    auto ldb_r = [&](int c, uint4* wv) {
        if constexpr (COUT == 128) {
            wv[0] = *(const uint4*)(wgt + (long)(c * 32 + kb) * COUT + nb);
            wv[1] = *(const uint4*)(wgt + (long)(c * 32 + kb + 16) * COUT + nb);
        } else {
            if (bact) wv[0] = *(const uint4*)(wgt + (long)(c * 32 + kb) * COUT + nb);
        }
    };
    auto store_st = [&](int st, const uint4* va, const uint4* wv) {
        __half* As = smb + st * SST;
        __half* Bs = As + ASZ;
        *(uint4*)(As + r * LDA + h) = va[0];
        if constexpr (TPR == 2) *(uint4*)(As + r * LDA + h + 8) = va[1];
        if constexpr (COUT == 128) {
            *(uint4*)(Bs + kb * LDB + nb) = wv[0];
            *(uint4*)(Bs + (kb + 16) * LDB + nb) = wv[1];
        } else {
            if (bact) *(uint4*)(Bs + kb * LDB + nb) = wv[0];
        }
    };

    int wm = wid / WN, wn = wid % WN;
    wmma::fragment<wmma::accumulator, 16, 16, 16, float> acc[MF][2];
#pragma unroll
    for (int i = 0; i < MF; i++)
#pragma unroll
        for (int j = 0; j < 2; j++) wmma::fill_fragment(acc[i][j], 0.f);

    uint4 va[2], wv[2], nva[2], nwv[2];
    va[0] = va[1] = wv[0] = wv[1] = make_uint4(0, 0, 0, 0);
    nva[0] = nva[1] = nwv[0] = nwv[1] = va[0];
    lda_r(0, va); ldb_r(0, wv);
    store_st(0, va, wv);
    __syncthreads();
    for (int c = 0; c < NC; c++) {
        int st = c & 1;
        if (c + 1 < NC) { lda_r(c + 1, nva); ldb_r(c + 1, nwv); }
        const __half* As = smb + st * SST;
        const __half* Bs = As + ASZ;
#pragma unroll
        for (int ks = 0; ks < 2; ks++) {
            wmma::fragment<wmma::matrix_b, 16, 16, 16, __half, wmma::row_major> fb[2];
#pragma unroll
            for (int j = 0; j < 2; j++)
                wmma::load_matrix_sync(fb[j], Bs + (ks * 16) * LDB + wn * 32 + j * 16, LDB);
#pragma unroll
            for (int i = 0; i < MF; i++) {
                wmma::fragment<wmma::matrix_a, 16, 16, 16, __half, wmma::row_major> fa;
                wmma::load_matrix_sync(fa, As + ((wm * MF + i) * 16) * LDA + ks * 16, LDA);
#pragma unroll
                for (int j = 0; j < 2; j++)
                    wmma::mma_sync(acc[i][j], fa, fb[j], acc[i][j]);
            }
        }
        if (c + 1 < NC) {
            store_st(st ^ 1, nva, nwv);
            __syncthreads();
        }
    }
    __syncthreads();
#pragma unroll
    for (int i = 0; i < MF; i++)
#pragma unroll
        for (int j = 0; j < 2; j++)
            wmma::store_matrix_sync(Cs + ((wm * MF + i) * 16) * LDC + wn * 32 + j * 16,
                                    acc[i][j], LDC, wmma::mem_row_major);
    __syncthreads();
    {
        int r2 = tid / TPR, ch0 = (tid % TPR) * (COUT / TPR);
        long base = (long)(m0 + r2) * COUT + ch0;
#pragma unroll
        for (int c = 0; c < COUT / TPR; c += 4) {
            float v0 = fmaxf(Cs[r2 * LDC + ch0 + c]     + bias[ch0 + c], 0.f);
            float v1 = fmaxf(Cs[r2 * LDC + ch0 + c + 1] + bias[ch0 + c + 1], 0.f);
            float v2 = fmaxf(Cs[r2 * LDC + ch0 + c + 2] + bias[ch0 + c + 2], 0.f);
            float v3 = fmaxf(Cs[r2 * LDC + ch0 + c + 3] + bias[ch0 + c + 3], 0.f);
            __half2 p0 = __floats2half2_rn(v0, v1);
            __half2 p1 = __floats2half2_rn(v2, v3);
            uint2 p;
            p.x = *reinterpret_cast<uint32_t*>(&p0);
            p.y = *reinterpret_cast<uint32_t*>(&p1);
            *(uint2*)(aout + base + c) = p;
        }
    }
}

// ============================================================================
// wmma GEMM fp16 2-term, fp32 out, double-buffered.  CTA: 64 x 128, BK=16.
// ============================================================================
template <int NTOT, int K, bool RELU>
__global__ __launch_bounds__(256) void mm_wm4(
    const __half* __restrict__ ain,
    const __half* __restrict__ whi, const __half* __restrict__ wlo,
    const float* __restrict__ bias, float* __restrict__ out) {
    constexpr int NC = K / 16;
    constexpr int LDA = 24, LDB = 136, LDC = 132;
    constexpr int ASZ = 64 * LDA, BSZ = 16 * LDB;
    constexpr int SST = ASZ + 2 * BSZ;
    constexpr int LOADSZ = 2 * SST * 2;
    constexpr int CSZ = 64 * LDC * 4;
    constexpr int SMSZ = (LOADSZ > CSZ) ? LOADSZ : CSZ;

    __shared__ __align__(16) char sm[SMSZ];
    __half* smb = (__half*)sm;
    float* Cs = (float*)sm;

    int tid = threadIdx.x, wid = tid >> 5;
    int m0 = blockIdx.x * 64, n0 = blockIdx.y * 128;
    int r = tid >> 2, h = (tid & 3) * 4;
    long mrow = m0 + r;
    int kb = tid >> 4, nb = (tid & 15) * 8;

    auto lda_r = [&](int c, uint2& va) {
        va = *(const uint2*)(ain + mrow * K + c * 16 + h);
    };
    auto ldb_r = [&](int c, uint4& wh, uint4& wl) {
        long g = (long)(c * 16 + kb) * NTOT + n0 + nb;
        wh = *(const uint4*)(whi + g);
        wl = *(const uint4*)(wlo + g);
    };
    auto store_st = [&](int st, const uint2& va, const uint4& wh, const uint4& wl) {
        __half* As = smb + st * SST;
        __half* BsH = As + ASZ;
        __half* BsL = BsH + BSZ;
        *(uint2*)(As + r * LDA + h) = va;
        *(uint4*)(BsH + kb * LDB + nb) = wh;
        *(uint4*)(BsL + kb * LDB + nb) = wl;
    };

    int wm = wid >> 2, wn = wid & 3;
    wmma::fragment<wmma::accumulator, 16, 16, 16, float> acc[2][2];
#pragma unroll
    for (int i = 0; i < 2; i++)
#pragma unroll
        for (int j = 0; j < 2; j++) wmma::fill_fragment(acc[i][j], 0.f);

    uint2 va, nva = make_uint2(0, 0);
    uint4 wh, wl, nwh = make_uint4(0, 0, 0, 0), nwl = nwh;
    lda_r(0, va); ldb_r(0, wh, wl);
    store_st(0, va, wh, wl);
    __syncthreads();
    for (int c = 0; c < NC; c++) {
        int st = c & 1;
        if (c + 1 < NC) { lda_r(c + 1, nva); ldb_r(c + 1, nwh, nwl); }
        const __half* As = smb + st * SST;
        const __half* BsH = As + ASZ;
        const __half* BsL = BsH + BSZ;
        wmma::fragment<wmma::matrix_b, 16, 16, 16, __half, wmma::row_major> fbh[2], fbl[2];
#pragma unroll
        for (int j = 0; j < 2; j++) {
            wmma::load_matrix_sync(fbh[j], BsH + wn * 32 + j * 16, LDB);
            wmma::load_matrix_sync(fbl[j], BsL + wn * 32 + j * 16, LDB);
        }
#pragma unroll
        for (int i = 0; i < 2; i++) {
            wmma::fragment<wmma::matrix_a, 16, 16, 16, __half, wmma::row_major> fa;
            wmma::load_matrix_sync(fa, As + ((wm * 2 + i) * 16) * LDA, LDA);
#pragma unroll
            for (int j = 0; j < 2; j++) {
                wmma::mma_sync(acc[i][j], fa, fbh[j], acc[i][j]);
                wmma::mma_sync(acc[i][j], fa, fbl[j], acc[i][j]);
            }
        }
        if (c + 1 < NC) {
            store_st(st ^ 1, nva, nwh, nwl);
            __syncthreads();
        }
    }
    __syncthreads();
#pragma unroll
    for (int i = 0; i < 2; i++)
#pragma unroll
        for (int j = 0; j < 2; j++)
            wmma::store_matrix_sync(Cs + ((wm * 2 + i) * 16) * LDC + wn * 32 + j * 16,
                                    acc[i][j], LDC, wmma::mem_row_major);
    __syncthreads();
    {
        int r2 = tid >> 2, ch0 = (tid & 3) * 32;
        long base = (long)(m0 + r2) * NTOT + n0 + ch0;
#pragma unroll
        for (int c = 0; c < 32; c += 4) {
            float4 v;
            v.x = Cs[r2 * LDC + ch0 + c]     + bias[n0 + ch0 + c];
            v.y = Cs[r2 * LDC + ch0 + c + 1] + bias[n0 + ch0 + c + 1];
            v.z = Cs[r2 * LDC + ch0 + c + 2] + bias[n0 + ch0 + c + 2];
            v.w = Cs[r2 * LDC + ch0 + c + 3] + bias[n0 + ch0 + c + 3];
            if (RELU) {
                v.x = fmaxf(v.x, 0.f); v.y = fmaxf(v.y, 0.f);
                v.z = fmaxf(v.z, 0.f); v.w = fmaxf(v.w, 0.f);
            }
            *(float4*)(out + base + c) = v;
        }
    }
}

// ============================================================================
// Persistent LSTM: 64 CTAs x 256 threads (K-split 2), all 32 steps in one
// launch.  W_hh tile (512x32 fp32) resident in smem; c in registers; h
// ping-pongs through global with a grid barrier (counter zeroed by memset).
// ============================================================================
__global__ __launch_bounds__(256) void lstm_all(
    const float* __restrict__ xg, const float* __restrict__ wthh,
    const float* __restrict__ done, float* __restrict__ hbuf0,
    float* __restrict__ hbuf1, float* __restrict__ cbuf,
    __half* __restrict__ hs, int* __restrict__ bar) {
    extern __shared__ float smf[];
    float* Ws  = smf;                 // [512][36]
    float* shh = Ws + 512 * 36;       // [16][520]
    float* red = shh + 16 * 520;      // [128][4]

    int tid = threadIdx.x;
    int n0 = blockIdx.x * 32;

    // Load W tile once: 512 rows x 32 cols.
#pragma unroll
    for (int i = 0; i < 16; i++) {
        int f = i * 256 + tid;
        int k = f >> 3, cc = (f & 7) * 4;
        *(float4*)&Ws[k * 36 + cc] = *(const float4*)&wthh[(long)k * 2048 + n0 + cc];
    }

    int ks = tid >> 7;        // K half: 0 or 1
    int lt = tid & 127;
    int tx = lt & 7, ty = lt >> 3;
    int u = (n0 >> 2) + tx;
    float creg = 0.f;
    if (ks == 0) creg = cbuf[ty * 512 + u];

    for (int t = 0; t < 32; t++) {
        const float* hin = (t & 1) ? hbuf1 : hbuf0;
        float* hout = (t & 1) ? hbuf0 : hbuf1;
        // stage masked h into smem
#pragma unroll
        for (int i = 0; i < 8; i++) {
            int idx4 = i * 256 + tid;
            int b = idx4 >> 7, q = idx4 & 127;
            float keep = 1.f - done[t * 16 + b];
            float4 v = ((const float4*)hin)[idx4];
            v.x *= keep; v.y *= keep; v.z *= keep; v.w *= keep;
            *(float4*)&shh[b * 520 + q * 4] = v;
        }
        __syncthreads();
        float a0 = 0.f, a1 = 0.f, a2 = 0.f, a3 = 0.f;
        int kbase = ks * 256;
        const float* hrow = shh + ty * 520 + kbase;
        const float* wbase = Ws + kbase * 36 + tx * 4;
#pragma unroll 8
        for (int kk = 0; kk < 256; kk++) {
            float a = hrow[kk];
            float4 w = *(const float4*)(wbase + kk * 36);
            a0 += a * w.x; a1 += a * w.y; a2 += a * w.z; a3 += a * w.w;
        }
        if (ks == 1) {
            *(float4*)&red[lt * 4] = make_float4(a0, a1, a2, a3);
        }
        __syncthreads();
        if (ks == 0) {
            float4 rr = *(const float4*)&red[lt * 4];
            float4 xv = *(const float4*)&xg[(long)(t * 16 + ty) * 2048 + n0 + tx * 4];
            float ig = a0 + rr.x + xv.x;
            float fg = a1 + rr.y + xv.y;
            float gg = a2 + rr.z + xv.z;
            float og = a3 + rr.w + xv.w;
            float keep = 1.f - done[t * 16 + ty];
            float cold = creg * keep;
            float si = 1.f / (1.f + expf(-ig));
            float sf = 1.f / (1.f + expf(-fg));
            float so = 1.f / (1.f + expf(-og));
            float cn = sf * cold + si * tanhf(gg);
            float hn = so * tanhf(cn);
            creg = cn;
            hout[ty * 512 + u] = hn;
            hs[(long)(t * 16 + ty) * 512 + u] = __float2half_rn(hn);
        }
        // grid barrier
        __threadfence();
        __syncthreads();
        if (tid == 0) {
            atomicAdd(bar, 1);
            int target = 64 * (t + 1);
            while (atomicAdd(bar, 0) < target) __nanosleep(64);
        }
        __syncthreads();
        __threadfence();
    }
    if (ks == 0) cbuf[ty * 512 + u] = creg;
}

// ---------------------------------------------------------------------------
extern "C" void kernel_launch(void* const* d_in, const int* in_sizes, int n_in,
                              void* d_out, int out_size) {
    (void)in_sizes; (void)n_in; (void)out_size;
    __half* hh = nullptr;
    float* fa = nullptr;
    cudaGetSymbolAddress((void**)&hh, g_hh);
    cudaGetSymbolAddress((void**)&fa, g_f);

    const float* x    = (const float*)d_in[0];
    const float* done = (const float*)d_in[1];
    const float* h0   = (const float*)d_in[2];
    const float* c0   = (const float*)d_in[3];
    const float* w11  = (const float*)d_in[4];
    const float* b11  = (const float*)d_in[5];
    const float* w12  = (const float*)d_in[6];
    const float* b12  = (const float*)d_in[7];
    const float* w21  = (const float*)d_in[8];
    const float* b21  = (const float*)d_in[9];
    const float* w22  = (const float*)d_in[10];
    const float* b22  = (const float*)d_in[11];
    const float* w31  = (const float*)d_in[12];
    const float* b31  = (const float*)d_in[13];
    const float* w32  = (const float*)d_in[14];
    const float* b32  = (const float*)d_in[15];
    const float* W_ih = (const float*)d_in[16];
    const float* W_hh = (const float*)d_in[17];
    const float* b_ih = (const float*)d_in[18];
    const float* b_hh = (const float*)d_in[19];
    const float* Wf   = (const float*)d_in[20];
    const float* bf   = (const float*)d_in[21];
    float* out = (float*)d_out;

    cudaFuncSetAttribute(ihw_prep_t, cudaFuncAttributeMaxDynamicSharedMemorySize, 69632);
    cudaFuncSetAttribute(lstm_all, cudaFuncAttributeMaxDynamicSharedMemorySize, 110592);

    // ---- prep ----
    xprep<<<14336, 256>>>(x, hh + O_X);
    convw_all<<<2244, 256>>>(w11, w12, w21, w22, w31, w32,
                             hh + O_W1, hh + O_W2, hh + O_W3,
                             hh + O_W4, hh + O_W5, hh + O_W6);
    ihw_prep_t<<<dim3(16, 16), 256, 69632>>>(W_ih, hh + O_WIHH, hh + O_WIHL);
    wf_prep<<<1024, 256>>>(Wf, hh + O_WFH, hh + O_WFL);
    perm_hh<<<4096, 256>>>(W_hh, fa + F_WTHH);
    bias_sum<<<8, 256>>>(b_ih, b_hh, fa + F_BG);
    cudaMemcpyAsync(fa + F_H0, h0, 8192 * sizeof(float), cudaMemcpyDeviceToDevice, 0);
    cudaMemcpyAsync(fa + F_C,  c0, 8192 * sizeof(float), cudaMemcpyDeviceToDevice, 0);
    cudaMemsetAsync(fa + F_BAR, 0, sizeof(int), 0);

    // ---- conv stack (single-term fp16, BK=32 double-buffered) ----
    conv_wm6<4, 32, 7, 32, 32, 1><<<24576, 256>>>(hh + O_X, hh + O_W1, b11, hh + O_A1);
    conv_wm6<32, 32, 6, 32, 32, 2><<<5120, 256>>>(hh + O_A1, hh + O_W2, b12, hh + O_A2);
    conv_wm6<32, 64, 5, 16, 16, 1><<<4096, 256>>>(hh + O_A2, hh + O_W3, b21, hh + O_A3);
    conv_wm6<64, 64, 4, 16, 16, 2><<<768, 256>>>(hh + O_A3, hh + O_W4, b22, hh + O_A4);
    conv_wm6<64, 128, 3, 8, 8, 1><<<1024, 256>>>(hh + O_A4, hh + O_W5, b31, hh + O_A5);
    conv_wm6<128, 128, 2, 8, 8, 2><<<128, 256>>>(hh + O_A5, hh + O_W6, b32, hh + O_F);

    // ---- LSTM input GEMM (512 x 2048 x 2048, 2-term weights) ----
    mm_wm4<2048, 2048, false><<<dim3(8, 16), 256>>>(
        hh + O_F, hh + O_WIHH, hh + O_WIHL, fa + F_BG, fa + F_XG);

    // ---- all 32 recurrent steps in one persistent kernel ----
    lstm_all<<<64, 256, 110592>>>(fa + F_XG, fa + F_WTHH, done,
                                  fa + F_H0, fa + F_H1, fa + F_C,
                                  hh + O_HS, (int*)(fa + F_BAR));

    // ---- final FC + relu into d_out ----
    mm_wm4<512, 512, true><<<dim3(8, 4), 256>>>(
        hh + O_HS, hh + O_WFH, hh + O_WFL, bf, out);

    // ---- hT, cT ----
    cudaMemcpyAsync(out + 262144, fa + F_H0, 8192 * sizeof(float),
                    cudaMemcpyDeviceToDevice, 0);
    cudaMemcpyAsync(out + 270336, fa + F_C, 8192 * sizeof(float),
                    cudaMemcpyDeviceToDevice, 0);
}